// round 3
// baseline (speedup 1.0000x reference)
#include <cuda_runtime.h>
#include <math.h>

// ---------------- problem constants ----------------
#define RB    128
#define NN    1024
#define RTOT  (RB*NN)        // 131072 rows
#define DIMT  40
#define ST    4              // seq len (HIST-1)
#define HDm   20             // head dim
#define FFND  256
#define HIDD  128
#define ED    4096
#define OBSD  200
#define RETD  192            // S*DIM + 32

typedef unsigned long long u64;

// ---------------- f32x2 packed helpers ----------------
__device__ __forceinline__ u64 f2pack(float lo, float hi) {
    u64 r; asm("mov.b64 %0,{%1,%2};" : "=l"(r) : "f"(lo), "f"(hi)); return r;
}
__device__ __forceinline__ void f2unpack(u64 v, float& lo, float& hi) {
    asm("mov.b64 {%0,%1},%2;" : "=f"(lo), "=f"(hi) : "l"(v));
}
__device__ __forceinline__ u64 f2dup(float x) { return f2pack(x, x); }
__device__ __forceinline__ u64 ffma2(u64 a, u64 b, u64 c) {
    u64 d; asm("fma.rn.f32x2 %0,%1,%2,%3;" : "=l"(d) : "l"(a), "l"(b), "l"(c)); return d;
}

// dot of a 40-float smem row with packed x2[20] (pairs along input dim)
__device__ __forceinline__ float dot40(const float* __restrict__ wrow, const u64* __restrict__ x2) {
    const ulonglong2* w = reinterpret_cast<const ulonglong2*>(wrow);
    u64 a0 = 0ULL, a1 = 0ULL, a2 = 0ULL, a3 = 0ULL;
    #pragma unroll
    for (int i = 0; i < 5; i++) {
        ulonglong2 p = w[2*i];
        ulonglong2 q = w[2*i+1];
        a0 = ffma2(p.x, x2[4*i+0], a0);
        a1 = ffma2(p.y, x2[4*i+1], a1);
        a2 = ffma2(q.x, x2[4*i+2], a2);
        a3 = ffma2(q.y, x2[4*i+3], a3);
    }
    float l0,h0,l1,h1,l2,h2,l3,h3;
    f2unpack(a0,l0,h0); f2unpack(a1,l1,h1); f2unpack(a2,l2,h2); f2unpack(a3,l3,h3);
    return ((l0+h0)+(l1+h1)) + ((l2+h2)+(l3+h3));
}

// dot of a 128-float smem row with packed x2[64]
__device__ __forceinline__ float dot128(const float* __restrict__ wrow, const u64* __restrict__ x2) {
    const ulonglong2* w = reinterpret_cast<const ulonglong2*>(wrow);
    u64 a0 = 0ULL, a1 = 0ULL, a2 = 0ULL, a3 = 0ULL;
    #pragma unroll
    for (int i = 0; i < 16; i++) {
        ulonglong2 p = w[2*i];
        ulonglong2 q = w[2*i+1];
        a0 = ffma2(p.x, x2[4*i+0], a0);
        a1 = ffma2(p.y, x2[4*i+1], a1);
        a2 = ffma2(q.x, x2[4*i+2], a2);
        a3 = ffma2(q.y, x2[4*i+3], a3);
    }
    float l0,h0,l1,h1,l2,h2,l3,h3;
    f2unpack(a0,l0,h0); f2unpack(a1,l1,h1); f2unpack(a2,l2,h2); f2unpack(a3,l3,h3);
    return ((l0+h0)+(l1+h1)) + ((l2+h2)+(l3+h3));
}

// ---------------- device workspaces (no cudaMalloc allowed) ----------------
__device__ float g_hT[(size_t)RETD * RTOT];    // feature-major: 0..159 = h, 160..191 = current_obs
__device__ float g_embT[(size_t)HIDD * RTOT];  // feature-major
__device__ float g_xl[(size_t)RTOT * HIDD];    // row-major (edge gather)
__device__ float g_xr[(size_t)RTOT * HIDD];
__device__ int   g_off[NN + 1];
__device__ int   g_srcs[ED];

// ---------------- CSR build (single block; same base graph for all batches) ----------------
__global__ void kcsr(const int* __restrict__ ei)
{
    __shared__ int cnt[NN];
    __shared__ int head[NN];
    const int tid = threadIdx.x;
    for (int i = tid; i < NN; i += blockDim.x) cnt[i] = 0;
    __syncthreads();
    for (int e = tid; e < ED; e += blockDim.x) atomicAdd(&cnt[ei[ED + e]], 1);
    __syncthreads();
    if (tid == 0) {
        int s = 0;
        for (int n = 0; n < NN; n++) { g_off[n] = s; head[n] = s; s += cnt[n]; }
        g_off[NN] = s;
    }
    __syncthreads();
    for (int e = tid; e < ED; e += blockDim.x) {
        int d = ei[ED + e];
        int pos = atomicAdd(&head[d], 1);
        g_srcs[pos] = ei[e];
    }
}

// ---------------- transformer kernel: smem layout (float offsets) ----------------
#define SW_QKV 0
#define SB_QKV 4800
#define SW_O   4920
#define SB_O   6520
#define SG1    6560
#define SBT1   6600
#define SG2    6640
#define SBT2   6680
#define SW1    6720
#define SFB1   16960
#define SW2T   17216
#define SFB2   27456
#define SPE    27496
#define SM_KT  27656   // floats -> 110,624 bytes

// 256 threads = 64 rows x 4 tokens. Each thread owns one token of one row.
__global__ void __launch_bounds__(256, 1)
kt_kernel(const float* __restrict__ obs,
          const float* __restrict__ wqkv, const float* __restrict__ bqkv,
          const float* __restrict__ wo,   const float* __restrict__ bo,
          const float* __restrict__ w1,   const float* __restrict__ b1f,
          const float* __restrict__ w2,   const float* __restrict__ b2f,
          const float* __restrict__ g1,   const float* __restrict__ bb1,
          const float* __restrict__ g2,   const float* __restrict__ bb2,
          const float* __restrict__ pe)
{
    extern __shared__ float sm[];
    const int tid  = threadIdx.x;
    const int rb   = tid >> 2;         // row within block (0..63)
    const int t    = tid & 3;          // token (0..3)
    const int r    = blockIdx.x * 64 + rb;
    const unsigned lane  = tid & 31;
    const unsigned qbase = lane & ~3u; // first lane of my token quad

    for (int i = tid; i < ST * DIMT; i += 256) sm[SPE + i] = pe[i];
    __syncthreads();

    // my token's h = obs[r, t, :] + pe[t]
    float h[DIMT];
    {
        const float4* orow = reinterpret_cast<const float4*>(obs + (size_t)r * OBSD + t * DIMT);
        #pragma unroll
        for (int i4 = 0; i4 < 10; i4++) {
            float4 v = orow[i4];
            h[i4*4+0] = v.x + sm[SPE + t*DIMT + i4*4+0];
            h[i4*4+1] = v.y + sm[SPE + t*DIMT + i4*4+1];
            h[i4*4+2] = v.z + sm[SPE + t*DIMT + i4*4+2];
            h[i4*4+3] = v.w + sm[SPE + t*DIMT + i4*4+3];
        }
    }

    const float isq = 0.223606797749979f;  // 1/sqrt(20)

    for (int l = 0; l < 3; l++) {
        __syncthreads();   // previous layer done reading weights
        {
            const float* p;
            p = wqkv + l*4800;  for (int i = tid; i < 4800;  i += 256) sm[SW_QKV+i] = p[i];
            p = bqkv + l*120;   for (int i = tid; i < 120;   i += 256) sm[SB_QKV+i] = p[i];
            p = wo   + l*1600;  for (int i = tid; i < 1600;  i += 256) sm[SW_O+i]   = p[i];
            p = bo   + l*40;    for (int i = tid; i < 40;    i += 256) sm[SB_O+i]   = p[i];
            p = g1   + l*40;    for (int i = tid; i < 40;    i += 256) sm[SG1+i]    = p[i];
            p = bb1  + l*40;    for (int i = tid; i < 40;    i += 256) sm[SBT1+i]   = p[i];
            p = g2   + l*40;    for (int i = tid; i < 40;    i += 256) sm[SG2+i]    = p[i];
            p = bb2  + l*40;    for (int i = tid; i < 40;    i += 256) sm[SBT2+i]   = p[i];
            p = w1   + l*10240; for (int i = tid; i < 10240; i += 256) sm[SW1+i]    = p[i];
            p = b1f  + l*256;   for (int i = tid; i < 256;   i += 256) sm[SFB1+i]   = p[i];
            p = w2   + l*10240; // transpose ffn_w2 (40x256) -> w2T[k][j]
            for (int i = tid; i < 10240; i += 256) { int j = i / 256, k = i % 256; sm[SW2T + k*DIMT + j] = p[i]; }
            p = b2f  + l*40;    for (int i = tid; i < 40;    i += 256) sm[SFB2+i]   = p[i];
        }
        __syncthreads();

        // ---- QKV for my token (packed input pairs) ----
        float qq[DIMT], kk[DIMT], vv[DIMT];
        {
            u64 h2[20];
            #pragma unroll
            for (int i = 0; i < 20; i++) h2[i] = f2pack(h[2*i], h[2*i+1]);
            #pragma unroll 4
            for (int j = 0; j < DIMT; j++)
                qq[j] = dot40(&sm[SW_QKV + j*DIMT], h2)        + sm[SB_QKV + j];
            #pragma unroll 4
            for (int j = 0; j < DIMT; j++)
                kk[j] = dot40(&sm[SW_QKV + (40+j)*DIMT], h2)   + sm[SB_QKV + 40 + j];
            #pragma unroll 4
            for (int j = 0; j < DIMT; j++)
                vv[j] = dot40(&sm[SW_QKV + (80+j)*DIMT], h2)   + sm[SB_QKV + 80 + j];
        }

        // ---- causal attention via quad shuffles (2 heads of 20) ----
        float o[DIMT];
        {
            float s0[ST], s1[ST];
            #pragma unroll
            for (int t2 = 0; t2 < ST; t2++) {
                float a = 0.f, b = 0.f;
                #pragma unroll
                for (int d = 0; d < HDm; d++) {
                    float kd = __shfl_sync(0xffffffffu, kk[d], qbase + t2, 32);
                    a += qq[d] * kd;
                }
                #pragma unroll
                for (int d = HDm; d < DIMT; d++) {
                    float kd = __shfl_sync(0xffffffffu, kk[d], qbase + t2, 32);
                    b += qq[d] * kd;
                }
                s0[t2] = a * isq;
                s1[t2] = b * isq;
            }
            float m0 = -1e30f, m1 = -1e30f;
            #pragma unroll
            for (int t2 = 0; t2 < ST; t2++) {
                if (t2 <= t) { m0 = fmaxf(m0, s0[t2]); m1 = fmaxf(m1, s1[t2]); }
            }
            float p0[ST], p1[ST], d0 = 0.f, d1 = 0.f;
            #pragma unroll
            for (int t2 = 0; t2 < ST; t2++) {
                p0[t2] = (t2 <= t) ? __expf(s0[t2] - m0) : 0.f;
                p1[t2] = (t2 <= t) ? __expf(s1[t2] - m1) : 0.f;
                d0 += p0[t2]; d1 += p1[t2];
            }
            const float i0 = 1.f / d0, i1 = 1.f / d1;
            #pragma unroll
            for (int d = 0; d < HDm; d++) {
                float a = 0.f;
                #pragma unroll
                for (int t2 = 0; t2 < ST; t2++)
                    a += p0[t2] * __shfl_sync(0xffffffffu, vv[d], qbase + t2, 32);
                o[d] = a * i0;
            }
            #pragma unroll
            for (int d = HDm; d < DIMT; d++) {
                float a = 0.f;
                #pragma unroll
                for (int t2 = 0; t2 < ST; t2++)
                    a += p1[t2] * __shfl_sync(0xffffffffu, vv[d], qbase + t2, 32);
                o[d] = a * i1;
            }
        }

        // ---- Wo projection + residual + LN1 ----
        float hc[DIMT];
        {
            u64 o2[20];
            #pragma unroll
            for (int i = 0; i < 20; i++) o2[i] = f2pack(o[2*i], o[2*i+1]);
            #pragma unroll 4
            for (int j = 0; j < DIMT; j++)
                hc[j] = h[j] + dot40(&sm[SW_O + j*DIMT], o2) + sm[SB_O + j];
        }
        {
            float mean = 0.f;
            #pragma unroll
            for (int i = 0; i < DIMT; i++) mean += hc[i];
            mean *= (1.f / DIMT);
            float var = 0.f;
            #pragma unroll
            for (int i = 0; i < DIMT; i++) { float d = hc[i] - mean; var += d * d; }
            var *= (1.f / DIMT);
            float rstd = rsqrtf(var + 1e-6f);
            #pragma unroll
            for (int i = 0; i < DIMT; i++) hc[i] = (hc[i] - mean) * rstd * sm[SG1 + i] + sm[SBT1 + i];
        }

        // ---- FFN 40 -> 256(relu) -> 40, fully packed ----
        {
            u64 hp[20];
            #pragma unroll
            for (int i = 0; i < 20; i++) hp[i] = f2pack(hc[2*i], hc[2*i+1]);
            u64 fa[20];
            #pragma unroll
            for (int j = 0; j < 20; j++) fa[j] = f2pack(sm[SFB2 + 2*j], sm[SFB2 + 2*j+1]);

            #pragma unroll 4
            for (int k = 0; k < FFND; k++) {
                float s = dot40(&sm[SW1 + k*DIMT], hp) + sm[SFB1 + k];
                s = fmaxf(s, 0.f);
                u64 s2 = f2dup(s);
                const ulonglong2* w2r = reinterpret_cast<const ulonglong2*>(&sm[SW2T + k*DIMT]);
                #pragma unroll
                for (int i = 0; i < 10; i++) {
                    ulonglong2 u = w2r[i];
                    fa[2*i]   = ffma2(u.x, s2, fa[2*i]);
                    fa[2*i+1] = ffma2(u.y, s2, fa[2*i+1]);
                }
            }
            #pragma unroll
            for (int j = 0; j < 20; j++) {
                float lo, hi;
                f2unpack(fa[j], lo, hi);
                hc[2*j]   += lo;
                hc[2*j+1] += hi;
            }
        }
        // LN2 -> h
        {
            float mean = 0.f;
            #pragma unroll
            for (int i = 0; i < DIMT; i++) mean += hc[i];
            mean *= (1.f / DIMT);
            float var = 0.f;
            #pragma unroll
            for (int i = 0; i < DIMT; i++) { float d = hc[i] - mean; var += d * d; }
            var *= (1.f / DIMT);
            float rstd = rsqrtf(var + 1e-6f);
            #pragma unroll
            for (int i = 0; i < DIMT; i++) h[i] = (hc[i] - mean) * rstd * sm[SG2 + i] + sm[SBT2 + i];
        }
    }

    // epilogue: feature-major h + current_obs (each thread writes its token's 40 features)
    #pragma unroll
    for (int i = 0; i < DIMT; i++)
        g_hT[(size_t)(t*DIMT + i) * RTOT + r] = h[i];
    {
        const float* orow = obs + (size_t)r * OBSD + 160 + t * 8;
        #pragma unroll
        for (int j = 0; j < 8; j++)
            g_hT[(size_t)(160 + t*8 + j) * RTOT + r] = orow[j];
    }
}

// ---------------- emb MLP: 192 -> 128 (relu) -> 128 (relu) ----------------
#define E_W1T 0
#define E_B1  24576
#define E_W2  24704
#define E_B2  41088
#define SM_E  41216   // floats -> 164,864 bytes

__global__ void __launch_bounds__(256)
kemb(const float* __restrict__ W1, const float* __restrict__ b1,
     const float* __restrict__ W2, const float* __restrict__ b2)
{
    extern __shared__ float sm[];
    const int tid = threadIdx.x;
    for (int idx = tid; idx < 24576; idx += 256) {
        int j = idx / RETD, i = idx % RETD;
        sm[E_W1T + i*HIDD + j] = W1[idx];           // transposed: contiguous in output j
    }
    for (int i = tid; i < HIDD;  i += 256) sm[E_B1 + i] = b1[i];
    for (int i = tid; i < 16384; i += 256) sm[E_W2 + i] = W2[i];
    for (int i = tid; i < HIDD;  i += 256) sm[E_B2 + i] = b2[i];
    __syncthreads();

    const int r = blockIdx.x * 256 + tid;

    // layer 1: packed output pairs
    u64 acc2[64];
    #pragma unroll
    for (int j = 0; j < 64; j++) acc2[j] = f2pack(sm[E_B1 + 2*j], sm[E_B1 + 2*j+1]);
    for (int i = 0; i < RETD; i++) {
        u64 xi2 = f2dup(g_hT[(size_t)i * RTOT + r]);
        const ulonglong2* wr = reinterpret_cast<const ulonglong2*>(&sm[E_W1T + i*HIDD]);
        #pragma unroll
        for (int j = 0; j < 32; j++) {
            ulonglong2 w = wr[j];
            acc2[2*j]   = ffma2(w.x, xi2, acc2[2*j]);
            acc2[2*j+1] = ffma2(w.y, xi2, acc2[2*j+1]);
        }
    }
    // relu in packed form
    #pragma unroll
    for (int j = 0; j < 64; j++) {
        float lo, hi;
        f2unpack(acc2[j], lo, hi);
        acc2[j] = f2pack(fmaxf(lo, 0.f), fmaxf(hi, 0.f));
    }

    // layer 2: packed input pairs (acc2 already pairs along input dim)
    #pragma unroll 2
    for (int j = 0; j < HIDD; j++) {
        float v = dot128(&sm[E_W2 + j*HIDD], acc2) + sm[E_B2 + j];
        g_embT[(size_t)j * RTOT + r] = fmaxf(v, 0.f);
    }
}

// ---------------- GAT projections: xl, xr (row-major for gather) ----------------
#define G_WL 0
#define G_BL 16384
#define G_WR 16512
#define G_BR 32896
#define SM_G 33024   // floats -> 132,096 bytes

__global__ void __launch_bounds__(256)
kxlr(const float* __restrict__ wl, const float* __restrict__ bl,
     const float* __restrict__ wr, const float* __restrict__ br)
{
    extern __shared__ float sm[];
    const int tid = threadIdx.x;
    for (int i = tid; i < 16384; i += 256) sm[G_WL + i] = wl[i];
    for (int i = tid; i < HIDD;  i += 256) sm[G_BL + i] = bl[i];
    for (int i = tid; i < 16384; i += 256) sm[G_WR + i] = wr[i];
    for (int i = tid; i < HIDD;  i += 256) sm[G_BR + i] = br[i];
    __syncthreads();

    const int r = blockIdx.x * 256 + tid;

    u64 in2[64];
    #pragma unroll
    for (int i = 0; i < 64; i++)
        in2[i] = f2pack(g_embT[(size_t)(2*i) * RTOT + r], g_embT[(size_t)(2*i+1) * RTOT + r]);

    #pragma unroll 1
    for (int side = 0; side < 2; side++) {
        const int wbase = side ? G_WR : G_WL;
        const int bbase = side ? G_BR : G_BL;
        float* outp = side ? g_xr : g_xl;
        for (int jb = 0; jb < 32; jb++) {
            float a0 = dot128(&sm[wbase + (jb*4+0)*HIDD], in2) + sm[bbase + jb*4+0];
            float a1 = dot128(&sm[wbase + (jb*4+1)*HIDD], in2) + sm[bbase + jb*4+1];
            float a2 = dot128(&sm[wbase + (jb*4+2)*HIDD], in2) + sm[bbase + jb*4+2];
            float a3 = dot128(&sm[wbase + (jb*4+3)*HIDD], in2) + sm[bbase + jb*4+3];
            *reinterpret_cast<float4*>(&outp[(size_t)r * HIDD + jb*4]) = make_float4(a0, a1, a2, a3);
        }
    }
}

// ---------------- GAT aggregation + final head (warp per node, no atomics) ----------------
__global__ void __launch_bounds__(256)
kgat(const float* __restrict__ att, const float* __restrict__ gbias,
     const float* __restrict__ Wq,  const float* __restrict__ bq,
     float* __restrict__ out)
{
    const int wid  = (blockIdx.x * 256 + threadIdx.x) >> 5;
    const int lane = threadIdx.x & 31;
    const int r = wid;
    const int b = r >> 10;      // / NN
    const int n = r & 1023;     // % NN

    const float4 xr4 = *reinterpret_cast<const float4*>(&g_xr[(size_t)r * HIDD + lane*4]);
    const float4 av  = *reinterpret_cast<const float4*>(&att[lane*4]);

    float4 acc = make_float4(0.f, 0.f, 0.f, 0.f);
    float den = 0.f;

    const int beg = g_off[n];
    const int end = g_off[n + 1];

    for (int idx = beg - 1; idx < end; idx++) {
        int src = (idx < beg) ? r : (g_srcs[idx] + (b << 10));   // first iteration = self loop
        const float4 xs = *reinterpret_cast<const float4*>(&g_xl[(size_t)src * HIDD + lane*4]);
        float4 m;
        m.x = xs.x + xr4.x; m.x = (m.x >= 0.f) ? m.x : 0.2f * m.x;
        m.y = xs.y + xr4.y; m.y = (m.y >= 0.f) ? m.y : 0.2f * m.y;
        m.z = xs.z + xr4.z; m.z = (m.z >= 0.f) ? m.z : 0.2f * m.z;
        m.w = xs.w + xr4.w; m.w = (m.w >= 0.f) ? m.w : 0.2f * m.w;
        float p = m.x*av.x + m.y*av.y + m.z*av.z + m.w*av.w;
        // reduce within 8-lane head group (lanes 8h..8h+7 hold head h)
        p += __shfl_xor_sync(0xffffffffu, p, 1);
        p += __shfl_xor_sync(0xffffffffu, p, 2);
        p += __shfl_xor_sync(0xffffffffu, p, 4);
        float wgt = __expf(p);   // scores tiny; softmax shift-invariant -> skip segment_max
        den += wgt;
        acc.x += wgt * xs.x;
        acc.y += wgt * xs.y;
        acc.z += wgt * xs.z;
        acc.w += wgt * xs.w;
    }

    const float4 gb = *reinterpret_cast<const float4*>(&gbias[lane*4]);
    const float invd = 1.f / den;
    float4 h2;
    h2.x = acc.x * invd + gb.x;
    h2.y = acc.y * invd + gb.y;
    h2.z = acc.z * invd + gb.z;
    h2.w = acc.w * invd + gb.w;

    float my = 0.f;
    #pragma unroll
    for (int j = 0; j < 8; j++) {
        const float4 wq = *reinterpret_cast<const float4*>(&Wq[j*HIDD + lane*4]);
        float p = wq.x*h2.x + wq.y*h2.y + wq.z*h2.z + wq.w*h2.w;
        p += __shfl_xor_sync(0xffffffffu, p, 16);
        p += __shfl_xor_sync(0xffffffffu, p, 8);
        p += __shfl_xor_sync(0xffffffffu, p, 4);
        p += __shfl_xor_sync(0xffffffffu, p, 2);
        p += __shfl_xor_sync(0xffffffffu, p, 1);
        if (lane == j) my = p + bq[j];
    }
    if (lane < 8) out[(size_t)r * 8 + lane] = my;
}

// ---------------- launch ----------------
extern "C" void kernel_launch(void* const* d_in, const int* in_sizes, int n_in,
                              void* d_out, int out_size)
{
    const float* obs      = (const float*)d_in[0];
    const int*   ei       = (const int*)  d_in[1];
    const float* W_emb1   = (const float*)d_in[2];
    const float* b_emb1   = (const float*)d_in[3];
    const float* W_emb2   = (const float*)d_in[4];
    const float* b_emb2   = (const float*)d_in[5];
    const float* tf_wqkv  = (const float*)d_in[6];
    const float* tf_bqkv  = (const float*)d_in[7];
    const float* tf_wo    = (const float*)d_in[8];
    const float* tf_bo    = (const float*)d_in[9];
    const float* ffn_w1   = (const float*)d_in[10];
    const float* ffn_b1   = (const float*)d_in[11];
    const float* ffn_w2   = (const float*)d_in[12];
    const float* ffn_b2   = (const float*)d_in[13];
    const float* ln1_g    = (const float*)d_in[14];
    const float* ln1_b    = (const float*)d_in[15];
    const float* ln2_g    = (const float*)d_in[16];
    const float* ln2_b    = (const float*)d_in[17];
    const float* gat_wl   = (const float*)d_in[18];
    const float* gat_bl   = (const float*)d_in[19];
    const float* gat_wr   = (const float*)d_in[20];
    const float* gat_br   = (const float*)d_in[21];
    const float* gat_att  = (const float*)d_in[22];
    const float* gat_bias = (const float*)d_in[23];
    const float* W_q      = (const float*)d_in[24];
    const float* b_q      = (const float*)d_in[25];
    const float* pe       = (const float*)d_in[26];

    cudaFuncSetAttribute(kt_kernel, cudaFuncAttributeMaxDynamicSharedMemorySize, SM_KT * 4);
    cudaFuncSetAttribute(kemb,      cudaFuncAttributeMaxDynamicSharedMemorySize, SM_E  * 4);
    cudaFuncSetAttribute(kxlr,      cudaFuncAttributeMaxDynamicSharedMemorySize, SM_G  * 4);

    kcsr<<<1, 256>>>(ei);
    kt_kernel<<<RTOT / 64, 256, SM_KT * 4>>>(obs,
        tf_wqkv, tf_bqkv, tf_wo, tf_bo,
        ffn_w1, ffn_b1, ffn_w2, ffn_b2,
        ln1_g, ln1_b, ln2_g, ln2_b, pe);
    kemb<<<RTOT / 256, 256, SM_E * 4>>>(W_emb1, b_emb1, W_emb2, b_emb2);
    kxlr<<<RTOT / 256, 256, SM_G * 4>>>(gat_wl, gat_bl, gat_wr, gat_br);
    kgat<<<(RTOT * 32) / 256, 256>>>(gat_att, gat_bias, W_q, b_q, (float*)d_out);
}

// round 9
// speedup vs baseline: 1.0970x; 1.0970x over previous
#include <cuda_runtime.h>
#include <math.h>

// ---------------- problem constants ----------------
#define RB    128
#define NN    1024
#define RTOT  (RB*NN)        // 131072 rows
#define DIMT  40
#define ST    4              // seq len (HIST-1)
#define HDm   20             // head dim
#define FFND  256
#define HIDD  128
#define ED    4096
#define OBSD  200
#define RETD  192            // S*DIM + 32

typedef unsigned long long u64;

// ---------------- f32x2 packed helpers ----------------
__device__ __forceinline__ u64 f2pack(float lo, float hi) {
    u64 r; asm("mov.b64 %0,{%1,%2};" : "=l"(r) : "f"(lo), "f"(hi)); return r;
}
__device__ __forceinline__ void f2unpack(u64 v, float& lo, float& hi) {
    asm("mov.b64 {%0,%1},%2;" : "=f"(lo), "=f"(hi) : "l"(v));
}
__device__ __forceinline__ u64 f2dup(float x) { return f2pack(x, x); }
__device__ __forceinline__ u64 ffma2(u64 a, u64 b, u64 c) {
    u64 d; asm("fma.rn.f32x2 %0,%1,%2,%3;" : "=l"(d) : "l"(a), "l"(b), "l"(c)); return d;
}
__device__ __forceinline__ u64 f2add(u64 a, u64 b) {
    u64 d; asm("add.rn.f32x2 %0,%1,%2;" : "=l"(d) : "l"(a), "l"(b)); return d;
}

// dot of a 40-float smem row with packed x2[20] (pairs along input dim)
__device__ __forceinline__ float dot40(const float* __restrict__ wrow, const u64* __restrict__ x2) {
    const ulonglong2* w = reinterpret_cast<const ulonglong2*>(wrow);
    u64 a0 = 0ULL, a1 = 0ULL, a2 = 0ULL, a3 = 0ULL;
    #pragma unroll
    for (int i = 0; i < 5; i++) {
        ulonglong2 p = w[2*i];
        ulonglong2 q = w[2*i+1];
        a0 = ffma2(p.x, x2[4*i+0], a0);
        a1 = ffma2(p.y, x2[4*i+1], a1);
        a2 = ffma2(q.x, x2[4*i+2], a2);
        a3 = ffma2(q.y, x2[4*i+3], a3);
    }
    float l0,h0,l1,h1,l2,h2,l3,h3;
    f2unpack(a0,l0,h0); f2unpack(a1,l1,h1); f2unpack(a2,l2,h2); f2unpack(a3,l3,h3);
    return ((l0+h0)+(l1+h1)) + ((l2+h2)+(l3+h3));
}

// ---------------- device workspaces (no cudaMalloc allowed) ----------------
__device__ float g_hT[(size_t)RETD * RTOT];    // feature-major: 0..159 = h, 160..191 = current_obs
__device__ float g_xl[(size_t)RTOT * HIDD];    // row-major (edge gather)
__device__ float g_xr[(size_t)RTOT * HIDD];
__device__ int   g_off[NN + 1];
__device__ int   g_srcs[ED];

// ---------------- CSR build (single block; same base graph for all batches) ----------------
__global__ void kcsr(const int* __restrict__ ei)
{
    __shared__ int cnt[NN];
    __shared__ int head[NN];
    const int tid = threadIdx.x;
    for (int i = tid; i < NN; i += blockDim.x) cnt[i] = 0;
    __syncthreads();
    for (int e = tid; e < ED; e += blockDim.x) atomicAdd(&cnt[ei[ED + e]], 1);
    __syncthreads();
    if (tid == 0) {
        int s = 0;
        for (int n = 0; n < NN; n++) { g_off[n] = s; head[n] = s; s += cnt[n]; }
        g_off[NN] = s;
    }
    __syncthreads();
    for (int e = tid; e < ED; e += blockDim.x) {
        int d = ei[ED + e];
        int pos = atomicAdd(&head[d], 1);
        g_srcs[pos] = ei[e];
    }
}

// ---------------- transformer kernel: smem layout (float offsets) ----------------
#define SW_QKV 0
#define SB_QKV 4800
#define SW_O   4920
#define SB_O   6520
#define SG1    6560
#define SBT1   6600
#define SG2    6640
#define SBT2   6680
#define SW1    6720
#define SFB1   16960
#define SW2T   17216
#define SFB2   27456
#define SPE    27496
#define SHC    27656            // hc buffer: 256 units x stride 44
#define SM_KT  (SHC + 256*44)   // 38920 floats -> 155,680 bytes

// 256 threads = 64 rows x 4 tokens. Each thread owns one token of one row.
__global__ void __launch_bounds__(256, 1)
kt_kernel(const float* __restrict__ obs,
          const float* __restrict__ wqkv, const float* __restrict__ bqkv,
          const float* __restrict__ wo,   const float* __restrict__ bo,
          const float* __restrict__ w1,   const float* __restrict__ b1f,
          const float* __restrict__ w2,   const float* __restrict__ b2f,
          const float* __restrict__ g1,   const float* __restrict__ bb1,
          const float* __restrict__ g2,   const float* __restrict__ bb2,
          const float* __restrict__ pe)
{
    extern __shared__ float sm[];
    const int tid  = threadIdx.x;
    const int rb   = tid >> 2;         // row within block (0..63)
    const int t    = tid & 3;          // token (0..3)
    const int r    = blockIdx.x * 64 + rb;
    const unsigned lane  = tid & 31;
    const unsigned qbase = lane & ~3u; // first lane of my token quad
    const int hcbase = SHC + tid * 44; // this thread's hc slot (stride 44 -> low conflicts)

    for (int i = tid; i < ST * DIMT; i += 256) sm[SPE + i] = pe[i];
    __syncthreads();

    // my token's h = obs[r, t, :] + pe[t]
    float h[DIMT];
    {
        const float4* orow = reinterpret_cast<const float4*>(obs + (size_t)r * OBSD + t * DIMT);
        #pragma unroll
        for (int i4 = 0; i4 < 10; i4++) {
            float4 v = orow[i4];
            h[i4*4+0] = v.x + sm[SPE + t*DIMT + i4*4+0];
            h[i4*4+1] = v.y + sm[SPE + t*DIMT + i4*4+1];
            h[i4*4+2] = v.z + sm[SPE + t*DIMT + i4*4+2];
            h[i4*4+3] = v.w + sm[SPE + t*DIMT + i4*4+3];
        }
    }

    const float isq = 0.223606797749979f;  // 1/sqrt(20)

    for (int l = 0; l < 3; l++) {
        __syncthreads();   // previous layer done reading weights + hcbuf
        {
            const float* p;
            p = wqkv + l*4800;  for (int i = tid; i < 4800;  i += 256) sm[SW_QKV+i] = p[i];
            p = bqkv + l*120;   for (int i = tid; i < 120;   i += 256) sm[SB_QKV+i] = p[i];
            p = wo   + l*1600;  for (int i = tid; i < 1600;  i += 256) sm[SW_O+i]   = p[i];
            p = bo   + l*40;    for (int i = tid; i < 40;    i += 256) sm[SB_O+i]   = p[i];
            p = g1   + l*40;    for (int i = tid; i < 40;    i += 256) sm[SG1+i]    = p[i];
            p = bb1  + l*40;    for (int i = tid; i < 40;    i += 256) sm[SBT1+i]   = p[i];
            p = g2   + l*40;    for (int i = tid; i < 40;    i += 256) sm[SG2+i]    = p[i];
            p = bb2  + l*40;    for (int i = tid; i < 40;    i += 256) sm[SBT2+i]   = p[i];
            p = w1   + l*10240; for (int i = tid; i < 10240; i += 256) sm[SW1+i]    = p[i];
            p = b1f  + l*256;   for (int i = tid; i < 256;   i += 256) sm[SFB1+i]   = p[i];
            p = w2   + l*10240; // transpose ffn_w2 (40x256) -> w2T[k][j]
            for (int i = tid; i < 10240; i += 256) { int j = i / 256, k = i % 256; sm[SW2T + k*DIMT + j] = p[i]; }
            p = b2f  + l*40;    for (int i = tid; i < 40;    i += 256) sm[SFB2+i]   = p[i];
        }
        __syncthreads();

        // ---- QKV for my token (packed input pairs) ----
        float qq[DIMT], kk[DIMT], vv[DIMT];
        {
            u64 h2[20];
            #pragma unroll
            for (int i = 0; i < 20; i++) h2[i] = f2pack(h[2*i], h[2*i+1]);
            #pragma unroll 4
            for (int j = 0; j < DIMT; j++)
                qq[j] = dot40(&sm[SW_QKV + j*DIMT], h2)        + sm[SB_QKV + j];
            #pragma unroll 4
            for (int j = 0; j < DIMT; j++)
                kk[j] = dot40(&sm[SW_QKV + (40+j)*DIMT], h2)   + sm[SB_QKV + 40 + j];
            #pragma unroll 4
            for (int j = 0; j < DIMT; j++)
                vv[j] = dot40(&sm[SW_QKV + (80+j)*DIMT], h2)   + sm[SB_QKV + 80 + j];
        }

        // ---- causal attention via quad shuffles (2 heads of 20) ----
        float o[DIMT];
        {
            float s0[ST], s1[ST];
            #pragma unroll
            for (int t2 = 0; t2 < ST; t2++) {
                float a = 0.f, b = 0.f;
                #pragma unroll
                for (int d = 0; d < HDm; d++) {
                    float kd = __shfl_sync(0xffffffffu, kk[d], qbase + t2, 32);
                    a += qq[d] * kd;
                }
                #pragma unroll
                for (int d = HDm; d < DIMT; d++) {
                    float kd = __shfl_sync(0xffffffffu, kk[d], qbase + t2, 32);
                    b += qq[d] * kd;
                }
                s0[t2] = a * isq;
                s1[t2] = b * isq;
            }
            float m0 = -1e30f, m1 = -1e30f;
            #pragma unroll
            for (int t2 = 0; t2 < ST; t2++) {
                if (t2 <= t) { m0 = fmaxf(m0, s0[t2]); m1 = fmaxf(m1, s1[t2]); }
            }
            float p0[ST], p1[ST], d0 = 0.f, d1 = 0.f;
            #pragma unroll
            for (int t2 = 0; t2 < ST; t2++) {
                p0[t2] = (t2 <= t) ? __expf(s0[t2] - m0) : 0.f;
                p1[t2] = (t2 <= t) ? __expf(s1[t2] - m1) : 0.f;
                d0 += p0[t2]; d1 += p1[t2];
            }
            const float i0 = 1.f / d0, i1 = 1.f / d1;
            #pragma unroll
            for (int d = 0; d < HDm; d++) {
                float a = 0.f;
                #pragma unroll
                for (int t2 = 0; t2 < ST; t2++)
                    a += p0[t2] * __shfl_sync(0xffffffffu, vv[d], qbase + t2, 32);
                o[d] = a * i0;
            }
            #pragma unroll
            for (int d = HDm; d < DIMT; d++) {
                float a = 0.f;
                #pragma unroll
                for (int t2 = 0; t2 < ST; t2++)
                    a += p1[t2] * __shfl_sync(0xffffffffu, vv[d], qbase + t2, 32);
                o[d] = a * i1;
            }
        }

        // ---- Wo projection + residual + LN1 ----
        float hc[DIMT];
        {
            u64 o2[20];
            #pragma unroll
            for (int i = 0; i < 20; i++) o2[i] = f2pack(o[2*i], o[2*i+1]);
            #pragma unroll 4
            for (int j = 0; j < DIMT; j++)
                hc[j] = h[j] + dot40(&sm[SW_O + j*DIMT], o2) + sm[SB_O + j];
        }
        {
            float mean = 0.f;
            #pragma unroll
            for (int i = 0; i < DIMT; i++) mean += hc[i];
            mean *= (1.f / DIMT);
            float var = 0.f;
            #pragma unroll
            for (int i = 0; i < DIMT; i++) { float d = hc[i] - mean; var += d * d; }
            var *= (1.f / DIMT);
            float rstd = rsqrtf(var + 1e-6f);
            #pragma unroll
            for (int i = 0; i < DIMT; i++) hc[i] = (hc[i] - mean) * rstd * sm[SG1 + i] + sm[SBT1 + i];
        }

        // ---- publish hc to smem for token-paired FFN ----
        #pragma unroll
        for (int i = 0; i < 10; i++)
            *reinterpret_cast<float4*>(&sm[hcbase + i*4]) =
                make_float4(hc[4*i], hc[4*i+1], hc[4*i+2], hc[4*i+3]);
        __syncthreads();

        // ---- FFN 40 -> 256(relu) -> 40: token-paired, k-split ----
        // thread (row rb, tp=t>>1, kh=t&1) handles tokens {2tp, 2tp+1} over k in [kh*128, kh*128+128)
        u64 fa[20];
        {
            const int tp = t >> 1, kh = t & 1;
            const int ba = SHC + (rb*4 + 2*tp) * 44;   // token 2tp
            const int bb2_ = ba + 44;                   // token 2tp+1
            u64 hpa[20], hpb[20];
            #pragma unroll
            for (int i = 0; i < 10; i++) {
                float4 va = *reinterpret_cast<const float4*>(&sm[ba  + i*4]);
                float4 vb = *reinterpret_cast<const float4*>(&sm[bb2_ + i*4]);
                hpa[2*i]   = f2pack(va.x, va.y); hpa[2*i+1] = f2pack(va.z, va.w);
                hpb[2*i]   = f2pack(vb.x, vb.y); hpb[2*i+1] = f2pack(vb.z, vb.w);
            }
            u64 faa[20], fab[20];
            #pragma unroll
            for (int j = 0; j < 20; j++) {
                u64 bz = (kh == 0) ? f2pack(sm[SFB2 + 2*j], sm[SFB2 + 2*j+1]) : 0ULL;
                faa[j] = bz; fab[j] = bz;   // bias counted once (kh==0 half only)
            }
            const int k0 = kh * 128;
            #pragma unroll 2
            for (int k = k0; k < k0 + 128; k++) {
                const ulonglong2* w1r = reinterpret_cast<const ulonglong2*>(&sm[SW1 + k*DIMT]);
                u64 A0=0,A1=0,A2=0,A3=0, B0=0,B1=0,B2=0,B3=0;
                #pragma unroll
                for (int i = 0; i < 5; i++) {
                    ulonglong2 p = w1r[2*i];
                    ulonglong2 q = w1r[2*i+1];
                    A0 = ffma2(p.x, hpa[4*i+0], A0); B0 = ffma2(p.x, hpb[4*i+0], B0);
                    A1 = ffma2(p.y, hpa[4*i+1], A1); B1 = ffma2(p.y, hpb[4*i+1], B1);
                    A2 = ffma2(q.x, hpa[4*i+2], A2); B2 = ffma2(q.x, hpb[4*i+2], B2);
                    A3 = ffma2(q.y, hpa[4*i+3], A3); B3 = ffma2(q.y, hpb[4*i+3], B3);
                }
                float l0,h0,l1,h1,l2,h2,l3,h3;
                f2unpack(A0,l0,h0); f2unpack(A1,l1,h1); f2unpack(A2,l2,h2); f2unpack(A3,l3,h3);
                float sa = ((l0+h0)+(l1+h1)) + ((l2+h2)+(l3+h3)) + sm[SFB1 + k];
                f2unpack(B0,l0,h0); f2unpack(B1,l1,h1); f2unpack(B2,l2,h2); f2unpack(B3,l3,h3);
                float sb = ((l0+h0)+(l1+h1)) + ((l2+h2)+(l3+h3)) + sm[SFB1 + k];
                sa = fmaxf(sa, 0.f); sb = fmaxf(sb, 0.f);
                u64 s2a = f2dup(sa), s2b = f2dup(sb);
                const ulonglong2* w2r = reinterpret_cast<const ulonglong2*>(&sm[SW2T + k*DIMT]);
                #pragma unroll
                for (int i = 0; i < 10; i++) {
                    ulonglong2 u = w2r[i];
                    faa[2*i]   = ffma2(u.x, s2a, faa[2*i]);
                    faa[2*i+1] = ffma2(u.y, s2a, faa[2*i+1]);
                    fab[2*i]   = ffma2(u.x, s2b, fab[2*i]);
                    fab[2*i+1] = ffma2(u.y, s2b, fab[2*i+1]);
                }
            }
            // combine with partner lane (lane^1 has same (row,tp), other k-half).
            // my own token = 2tp+kh -> slot kh is the one I keep.
            #pragma unroll
            for (int j = 0; j < 20; j++) {
                u64 send = (kh == 0) ? fab[j] : faa[j];    // the slot I don't need
                u64 recv = __shfl_xor_sync(0xffffffffu, send, 1);
                u64 mine = (kh == 0) ? faa[j] : fab[j];
                fa[j] = f2add(mine, recv);
            }
        }

        // ---- reload own hc, residual + LN2 -> h ----
        #pragma unroll
        for (int i = 0; i < 10; i++) {
            float4 v = *reinterpret_cast<const float4*>(&sm[hcbase + i*4]);
            hc[4*i] = v.x; hc[4*i+1] = v.y; hc[4*i+2] = v.z; hc[4*i+3] = v.w;
        }
        #pragma unroll
        for (int j = 0; j < 20; j++) {
            float lo, hi;
            f2unpack(fa[j], lo, hi);
            hc[2*j]   += lo;
            hc[2*j+1] += hi;
        }
        {
            float mean = 0.f;
            #pragma unroll
            for (int i = 0; i < DIMT; i++) mean += hc[i];
            mean *= (1.f / DIMT);
            float var = 0.f;
            #pragma unroll
            for (int i = 0; i < DIMT; i++) { float d = hc[i] - mean; var += d * d; }
            var *= (1.f / DIMT);
            float rstd = rsqrtf(var + 1e-6f);
            #pragma unroll
            for (int i = 0; i < DIMT; i++) h[i] = (hc[i] - mean) * rstd * sm[SG2 + i] + sm[SBT2 + i];
        }
    }

    // epilogue: feature-major h + current_obs (each thread writes its token's 40 features)
    #pragma unroll
    for (int i = 0; i < DIMT; i++)
        g_hT[(size_t)(t*DIMT + i) * RTOT + r] = h[i];
    {
        const float* orow = obs + (size_t)r * OBSD + 160 + t * 8;
        #pragma unroll
        for (int j = 0; j < 8; j++)
            g_hT[(size_t)(160 + t*8 + j) * RTOT + r] = orow[j];
    }
}

// ---------------- fused dense chain: emb1 -> relu -> emb2 -> relu -> xl, xr ----------------
// Block-GEMM: 128 rows x 128 outs per block, thread tile 8x8.
#define DS_STRIDE 132
#define DSA 0                          // A^T buffer: K x 132 (K up to 192)
#define DSB (192*DS_STRIDE)            // B buffer:   K x 132
#define SM_D (2*192*DS_STRIDE)         // 50688 floats -> 202,752 bytes

template<int K>
__device__ __forceinline__ void dgemm_phase(const float* __restrict__ sm,
                                            int tr, int tc,
                                            const float* __restrict__ bias,
                                            u64* acc)
{
    #pragma unroll
    for (int p = 0; p < 4; p++) {
        u64 bp = f2pack(bias[tc*8 + 2*p], bias[tc*8 + 2*p + 1]);
        #pragma unroll
        for (int r = 0; r < 8; r++) acc[r*4 + p] = bp;
    }
    #pragma unroll 4
    for (int k = 0; k < K; k++) {
        float4 a0 = *reinterpret_cast<const float4*>(&sm[DSA + k*DS_STRIDE + tr*8]);
        float4 a1 = *reinterpret_cast<const float4*>(&sm[DSA + k*DS_STRIDE + tr*8 + 4]);
        const ulonglong2* bp2 = reinterpret_cast<const ulonglong2*>(&sm[DSB + k*DS_STRIDE + tc*8]);
        ulonglong2 b01 = bp2[0];
        ulonglong2 b23 = bp2[1];
        u64 ad[8];
        ad[0]=f2dup(a0.x); ad[1]=f2dup(a0.y); ad[2]=f2dup(a0.z); ad[3]=f2dup(a0.w);
        ad[4]=f2dup(a1.x); ad[5]=f2dup(a1.y); ad[6]=f2dup(a1.z); ad[7]=f2dup(a1.w);
        #pragma unroll
        for (int rr = 0; rr < 8; rr++) {
            acc[rr*4+0] = ffma2(ad[rr], b01.x, acc[rr*4+0]);
            acc[rr*4+1] = ffma2(ad[rr], b01.y, acc[rr*4+1]);
            acc[rr*4+2] = ffma2(ad[rr], b23.x, acc[rr*4+2]);
            acc[rr*4+3] = ffma2(ad[rr], b23.y, acc[rr*4+3]);
        }
    }
}

// relu + write acc as transposed activations into DSA (next phase's A^T)
__device__ __forceinline__ void store_act(float* __restrict__ sm, int tr, int tc, const u64* acc)
{
    #pragma unroll
    for (int rr = 0; rr < 8; rr++) {
        #pragma unroll
        for (int p = 0; p < 4; p++) {
            float lo, hi;
            f2unpack(acc[rr*4+p], lo, hi);
            lo = fmaxf(lo, 0.f); hi = fmaxf(hi, 0.f);
            sm[DSA + (tc*8 + 2*p    )*DS_STRIDE + tr*8 + rr] = lo;
            sm[DSA + (tc*8 + 2*p + 1)*DS_STRIDE + tr*8 + rr] = hi;
        }
    }
}

// stage a 128x128 weight matrix W[j][k] into DSB as B[k][j]
__device__ __forceinline__ void stage_b128(float* __restrict__ sm, const float* __restrict__ W, int tid)
{
    for (int v = tid; v < 128*32; v += 256) {
        int j = v >> 5, k0 = (v & 31) * 4;
        float4 w = *reinterpret_cast<const float4*>(&W[j*128 + k0]);
        sm[DSB + (k0+0)*DS_STRIDE + j] = w.x;
        sm[DSB + (k0+1)*DS_STRIDE + j] = w.y;
        sm[DSB + (k0+2)*DS_STRIDE + j] = w.z;
        sm[DSB + (k0+3)*DS_STRIDE + j] = w.w;
    }
}

__global__ void __launch_bounds__(256, 1)
kdense(const float* __restrict__ W1, const float* __restrict__ b1,
       const float* __restrict__ W2, const float* __restrict__ b2,
       const float* __restrict__ wl, const float* __restrict__ bl,
       const float* __restrict__ wr, const float* __restrict__ br)
{
    extern __shared__ float sm[];
    const int tid = threadIdx.x;
    const int tr = tid >> 4;       // row group 0..15
    const int tc = tid & 15;       // out group 0..15
    const int r0 = blockIdx.x * 128;

    // stage phase-1 A^T (g_hT is feature-major => direct) and B = W1^T (W1 is [128][192])
    for (int v = tid; v < 192*32; v += 256) {
        int f = v >> 5, c = v & 31;
        *reinterpret_cast<float4*>(&sm[DSA + f*DS_STRIDE + c*4]) =
            *reinterpret_cast<const float4*>(&g_hT[(size_t)f * RTOT + r0 + c*4]);
    }
    for (int v = tid; v < 128*48; v += 256) {
        int j = v / 48, k0 = (v % 48) * 4;
        float4 w = *reinterpret_cast<const float4*>(&W1[j*192 + k0]);
        sm[DSB + (k0+0)*DS_STRIDE + j] = w.x;
        sm[DSB + (k0+1)*DS_STRIDE + j] = w.y;
        sm[DSB + (k0+2)*DS_STRIDE + j] = w.z;
        sm[DSB + (k0+3)*DS_STRIDE + j] = w.w;
    }
    __syncthreads();

    u64 acc[32];

    // phase 1: l1 = relu(ret @ W1^T + b1), K=192
    dgemm_phase<192>(sm, tr, tc, b1, acc);
    __syncthreads();                    // all reads of A/B done
    store_act(sm, tr, tc, acc);         // DSA <- l1^T (with relu)
    stage_b128(sm, W2, tid);            // DSB <- W2^T
    __syncthreads();

    // phase 2: l2 = relu(l1 @ W2^T + b2), K=128
    dgemm_phase<128>(sm, tr, tc, b2, acc);
    __syncthreads();
    store_act(sm, tr, tc, acc);         // DSA <- emb^T (with relu)
    stage_b128(sm, wl, tid);            // DSB <- WL^T
    __syncthreads();

    // phase 3: xl = emb @ WL^T + bl (no relu)
    dgemm_phase<128>(sm, tr, tc, bl, acc);
    #pragma unroll
    for (int rr = 0; rr < 8; rr++) {
        float o0,o1,o2,o3,o4,o5,o6,o7;
        f2unpack(acc[rr*4+0], o0, o1);
        f2unpack(acc[rr*4+1], o2, o3);
        f2unpack(acc[rr*4+2], o4, o5);
        f2unpack(acc[rr*4+3], o6, o7);
        size_t row = (size_t)(r0 + tr*8 + rr);
        *reinterpret_cast<float4*>(&g_xl[row*HIDD + tc*8    ]) = make_float4(o0,o1,o2,o3);
        *reinterpret_cast<float4*>(&g_xl[row*HIDD + tc*8 + 4]) = make_float4(o4,o5,o6,o7);
    }
    __syncthreads();                    // WL reads done
    stage_b128(sm, wr, tid);            // DSB <- WR^T
    __syncthreads();

    // phase 4: xr = emb @ WR^T + br (no relu)
    dgemm_phase<128>(sm, tr, tc, br, acc);
    #pragma unroll
    for (int rr = 0; rr < 8; rr++) {
        float o0,o1,o2,o3,o4,o5,o6,o7;
        f2unpack(acc[rr*4+0], o0, o1);
        f2unpack(acc[rr*4+1], o2, o3);
        f2unpack(acc[rr*4+2], o4, o5);
        f2unpack(acc[rr*4+3], o6, o7);
        size_t row = (size_t)(r0 + tr*8 + rr);
        *reinterpret_cast<float4*>(&g_xr[row*HIDD + tc*8    ]) = make_float4(o0,o1,o2,o3);
        *reinterpret_cast<float4*>(&g_xr[row*HIDD + tc*8 + 4]) = make_float4(o4,o5,o6,o7);
    }
}

// ---------------- GAT aggregation + final head (warp per node, no atomics) ----------------
__global__ void __launch_bounds__(256)
kgat(const float* __restrict__ att, const float* __restrict__ gbias,
     const float* __restrict__ Wq,  const float* __restrict__ bq,
     float* __restrict__ out)
{
    const int wid  = (blockIdx.x * 256 + threadIdx.x) >> 5;
    const int lane = threadIdx.x & 31;
    const int r = wid;
    const int b = r >> 10;      // / NN
    const int n = r & 1023;     // % NN

    const float4 xr4 = *reinterpret_cast<const float4*>(&g_xr[(size_t)r * HIDD + lane*4]);
    const float4 av  = *reinterpret_cast<const float4*>(&att[lane*4]);

    float4 acc = make_float4(0.f, 0.f, 0.f, 0.f);
    float den = 0.f;

    const int beg = g_off[n];
    const int end = g_off[n + 1];

    for (int idx = beg - 1; idx < end; idx++) {
        int src = (idx < beg) ? r : (g_srcs[idx] + (b << 10));   // first iteration = self loop
        const float4 xs = *reinterpret_cast<const float4*>(&g_xl[(size_t)src * HIDD + lane*4]);
        float4 m;
        m.x = xs.x + xr4.x; m.x = (m.x >= 0.f) ? m.x : 0.2f * m.x;
        m.y = xs.y + xr4.y; m.y = (m.y >= 0.f) ? m.y : 0.2f * m.y;
        m.z = xs.z + xr4.z; m.z = (m.z >= 0.f) ? m.z : 0.2f * m.z;
        m.w = xs.w + xr4.w; m.w = (m.w >= 0.f) ? m.w : 0.2f * m.w;
        float p = m.x*av.x + m.y*av.y + m.z*av.z + m.w*av.w;
        // reduce within 8-lane head group (lanes 8h..8h+7 hold head h)
        p += __shfl_xor_sync(0xffffffffu, p, 1);
        p += __shfl_xor_sync(0xffffffffu, p, 2);
        p += __shfl_xor_sync(0xffffffffu, p, 4);
        float wgt = __expf(p);   // scores tiny; softmax shift-invariant -> skip segment_max
        den += wgt;
        acc.x += wgt * xs.x;
        acc.y += wgt * xs.y;
        acc.z += wgt * xs.z;
        acc.w += wgt * xs.w;
    }

    const float4 gb = *reinterpret_cast<const float4*>(&gbias[lane*4]);
    const float invd = 1.f / den;
    float4 h2;
    h2.x = acc.x * invd + gb.x;
    h2.y = acc.y * invd + gb.y;
    h2.z = acc.z * invd + gb.z;
    h2.w = acc.w * invd + gb.w;

    float my = 0.f;
    #pragma unroll
    for (int j = 0; j < 8; j++) {
        const float4 wq = *reinterpret_cast<const float4*>(&Wq[j*HIDD + lane*4]);
        float p = wq.x*h2.x + wq.y*h2.y + wq.z*h2.z + wq.w*h2.w;
        p += __shfl_xor_sync(0xffffffffu, p, 16);
        p += __shfl_xor_sync(0xffffffffu, p, 8);
        p += __shfl_xor_sync(0xffffffffu, p, 4);
        p += __shfl_xor_sync(0xffffffffu, p, 2);
        p += __shfl_xor_sync(0xffffffffu, p, 1);
        if (lane == j) my = p + bq[j];
    }
    if (lane < 8) out[(size_t)r * 8 + lane] = my;
}

// ---------------- launch ----------------
extern "C" void kernel_launch(void* const* d_in, const int* in_sizes, int n_in,
                              void* d_out, int out_size)
{
    const float* obs      = (const float*)d_in[0];
    const int*   ei       = (const int*)  d_in[1];
    const float* W_emb1   = (const float*)d_in[2];
    const float* b_emb1   = (const float*)d_in[3];
    const float* W_emb2   = (const float*)d_in[4];
    const float* b_emb2   = (const float*)d_in[5];
    const float* tf_wqkv  = (const float*)d_in[6];
    const float* tf_bqkv  = (const float*)d_in[7];
    const float* tf_wo    = (const float*)d_in[8];
    const float* tf_bo    = (const float*)d_in[9];
    const float* ffn_w1   = (const float*)d_in[10];
    const float* ffn_b1   = (const float*)d_in[11];
    const float* ffn_w2   = (const float*)d_in[12];
    const float* ffn_b2   = (const float*)d_in[13];
    const float* ln1_g    = (const float*)d_in[14];
    const float* ln1_b    = (const float*)d_in[15];
    const float* ln2_g    = (const float*)d_in[16];
    const float* ln2_b    = (const float*)d_in[17];
    const float* gat_wl   = (const float*)d_in[18];
    const float* gat_bl   = (const float*)d_in[19];
    const float* gat_wr   = (const float*)d_in[20];
    const float* gat_br   = (const float*)d_in[21];
    const float* gat_att  = (const float*)d_in[22];
    const float* gat_bias = (const float*)d_in[23];
    const float* W_q      = (const float*)d_in[24];
    const float* b_q      = (const float*)d_in[25];
    const float* pe       = (const float*)d_in[26];

    cudaFuncSetAttribute(kt_kernel, cudaFuncAttributeMaxDynamicSharedMemorySize, SM_KT * 4);
    cudaFuncSetAttribute(kdense,    cudaFuncAttributeMaxDynamicSharedMemorySize, SM_D * 4);

    kcsr<<<1, 256>>>(ei);
    kt_kernel<<<RTOT / 64, 256, SM_KT * 4>>>(obs,
        tf_wqkv, tf_bqkv, tf_wo, tf_bo,
        ffn_w1, ffn_b1, ffn_w2, ffn_b2,
        ln1_g, ln1_b, ln2_g, ln2_b, pe);
    kdense<<<RTOT / 128, 256, SM_D * 4>>>(W_emb1, b_emb1, W_emb2, b_emb2,
                                          gat_wl, gat_bl, gat_wr, gat_br);
    kgat<<<(RTOT * 32) / 256, 256>>>(gat_att, gat_bias, W_q, b_q, (float*)d_out);
}

// round 16
// speedup vs baseline: 1.1003x; 1.0030x over previous
#include <cuda_runtime.h>
#include <math.h>

// ---------------- problem constants ----------------
#define RB    128
#define NN    1024
#define RTOT  (RB*NN)        // 131072 rows
#define DIMT  40
#define ST    4              // seq len (HIST-1)
#define HDm   20             // head dim
#define FFND  256
#define HIDD  128
#define ED    4096
#define OBSD  200
#define RETD  192            // S*DIM + 32

typedef unsigned long long u64;

// ---------------- f32x2 packed helpers ----------------
__device__ __forceinline__ u64 f2pack(float lo, float hi) {
    u64 r; asm("mov.b64 %0,{%1,%2};" : "=l"(r) : "f"(lo), "f"(hi)); return r;
}
__device__ __forceinline__ void f2unpack(u64 v, float& lo, float& hi) {
    asm("mov.b64 {%0,%1},%2;" : "=f"(lo), "=f"(hi) : "l"(v));
}
__device__ __forceinline__ u64 f2dup(float x) { return f2pack(x, x); }
__device__ __forceinline__ u64 ffma2(u64 a, u64 b, u64 c) {
    u64 d; asm("fma.rn.f32x2 %0,%1,%2,%3;" : "=l"(d) : "l"(a), "l"(b), "l"(c)); return d;
}
__device__ __forceinline__ u64 f2add(u64 a, u64 b) {
    u64 d; asm("add.rn.f32x2 %0,%1,%2;" : "=l"(d) : "l"(a), "l"(b)); return d;
}

// dot of a 40-float smem row with packed x2[20] (pairs along input dim)
__device__ __forceinline__ float dot40(const float* __restrict__ wrow, const u64* __restrict__ x2) {
    const ulonglong2* w = reinterpret_cast<const ulonglong2*>(wrow);
    u64 a0 = 0ULL, a1 = 0ULL, a2 = 0ULL, a3 = 0ULL;
    #pragma unroll
    for (int i = 0; i < 5; i++) {
        ulonglong2 p = w[2*i];
        ulonglong2 q = w[2*i+1];
        a0 = ffma2(p.x, x2[4*i+0], a0);
        a1 = ffma2(p.y, x2[4*i+1], a1);
        a2 = ffma2(q.x, x2[4*i+2], a2);
        a3 = ffma2(q.y, x2[4*i+3], a3);
    }
    float l0,h0,l1,h1,l2,h2,l3,h3;
    f2unpack(a0,l0,h0); f2unpack(a1,l1,h1); f2unpack(a2,l2,h2); f2unpack(a3,l3,h3);
    return ((l0+h0)+(l1+h1)) + ((l2+h2)+(l3+h3));
}

// ---------------- device workspaces (no cudaMalloc allowed) ----------------
__device__ float g_hT[(size_t)RETD * RTOT];    // feature-major: 0..159 = h, 160..191 = current_obs
__device__ float g_xl[(size_t)RTOT * HIDD];    // row-major (edge gather)
__device__ float g_xr[(size_t)RTOT * HIDD];
__device__ int   g_off[NN + 1];
__device__ int   g_srcs[ED];

// ---------------- CSR build (single block; same base graph for all batches) ----------------
__global__ void kcsr(const int* __restrict__ ei)
{
    __shared__ int cnt[NN];
    __shared__ int head[NN];
    const int tid = threadIdx.x;
    for (int i = tid; i < NN; i += blockDim.x) cnt[i] = 0;
    __syncthreads();
    for (int e = tid; e < ED; e += blockDim.x) atomicAdd(&cnt[ei[ED + e]], 1);
    __syncthreads();
    if (tid == 0) {
        int s = 0;
        for (int n = 0; n < NN; n++) { g_off[n] = s; head[n] = s; s += cnt[n]; }
        g_off[NN] = s;
    }
    __syncthreads();
    for (int e = tid; e < ED; e += blockDim.x) {
        int d = ei[ED + e];
        int pos = atomicAdd(&head[d], 1);
        g_srcs[pos] = ei[e];
    }
}

// ---------------- transformer kernel: smem layout (float offsets) ----------------
#define SW_QKV 0
#define SB_QKV 4800
#define SW_O   4920
#define SB_O   6520
#define SG1    6560
#define SBT1   6600
#define SG2    6640
#define SBT2   6680
#define SW1    6720
#define SFB1   16960
#define SW2T   17216
#define SFB2   27456
#define SPE    27496
#define SHC    27656            // hc buffer: 256 units x stride 44
#define SM_KT  (SHC + 256*44)   // 38920 floats -> 155,680 bytes

// 256 threads = 64 rows x 4 tokens. Each thread owns one token of one row.
__global__ void __launch_bounds__(256, 1)
kt_kernel(const float* __restrict__ obs,
          const float* __restrict__ wqkv, const float* __restrict__ bqkv,
          const float* __restrict__ wo,   const float* __restrict__ bo,
          const float* __restrict__ w1,   const float* __restrict__ b1f,
          const float* __restrict__ w2,   const float* __restrict__ b2f,
          const float* __restrict__ g1,   const float* __restrict__ bb1,
          const float* __restrict__ g2,   const float* __restrict__ bb2,
          const float* __restrict__ pe)
{
    extern __shared__ float sm[];
    const int tid  = threadIdx.x;
    const int rb   = tid >> 2;         // row within block (0..63)
    const int t    = tid & 3;          // token (0..3)
    const int r    = blockIdx.x * 64 + rb;
    const unsigned lane  = tid & 31;
    const unsigned qbase = lane & ~3u; // first lane of my token quad
    const int hcbase = SHC + tid * 44; // this thread's hc slot (stride 44 -> low conflicts)

    for (int i = tid; i < ST * DIMT; i += 256) sm[SPE + i] = pe[i];
    __syncthreads();

    // my token's h = obs[r, t, :] + pe[t]
    float h[DIMT];
    {
        const float4* orow = reinterpret_cast<const float4*>(obs + (size_t)r * OBSD + t * DIMT);
        #pragma unroll
        for (int i4 = 0; i4 < 10; i4++) {
            float4 v = orow[i4];
            h[i4*4+0] = v.x + sm[SPE + t*DIMT + i4*4+0];
            h[i4*4+1] = v.y + sm[SPE + t*DIMT + i4*4+1];
            h[i4*4+2] = v.z + sm[SPE + t*DIMT + i4*4+2];
            h[i4*4+3] = v.w + sm[SPE + t*DIMT + i4*4+3];
        }
    }

    const float isq = 0.223606797749979f;  // 1/sqrt(20)

    for (int l = 0; l < 3; l++) {
        __syncthreads();   // previous layer done reading weights + hcbuf
        {
            const float* p;
            p = wqkv + l*4800;  for (int i = tid; i < 4800;  i += 256) sm[SW_QKV+i] = p[i];
            p = bqkv + l*120;   for (int i = tid; i < 120;   i += 256) sm[SB_QKV+i] = p[i];
            p = wo   + l*1600;  for (int i = tid; i < 1600;  i += 256) sm[SW_O+i]   = p[i];
            p = bo   + l*40;    for (int i = tid; i < 40;    i += 256) sm[SB_O+i]   = p[i];
            p = g1   + l*40;    for (int i = tid; i < 40;    i += 256) sm[SG1+i]    = p[i];
            p = bb1  + l*40;    for (int i = tid; i < 40;    i += 256) sm[SBT1+i]   = p[i];
            p = g2   + l*40;    for (int i = tid; i < 40;    i += 256) sm[SG2+i]    = p[i];
            p = bb2  + l*40;    for (int i = tid; i < 40;    i += 256) sm[SBT2+i]   = p[i];
            p = w1   + l*10240; for (int i = tid; i < 10240; i += 256) sm[SW1+i]    = p[i];
            p = b1f  + l*256;   for (int i = tid; i < 256;   i += 256) sm[SFB1+i]   = p[i];
            p = w2   + l*10240; // transpose ffn_w2 (40x256) -> w2T[k][j]
            for (int i = tid; i < 10240; i += 256) { int j = i / 256, k = i % 256; sm[SW2T + k*DIMT + j] = p[i]; }
            p = b2f  + l*40;    for (int i = tid; i < 40;    i += 256) sm[SFB2+i]   = p[i];
        }
        __syncthreads();

        // ---- QKV for my token (packed input pairs) ----
        float qq[DIMT], kk[DIMT], vv[DIMT];
        {
            u64 h2[20];
            #pragma unroll
            for (int i = 0; i < 20; i++) h2[i] = f2pack(h[2*i], h[2*i+1]);
            #pragma unroll 4
            for (int j = 0; j < DIMT; j++)
                qq[j] = dot40(&sm[SW_QKV + j*DIMT], h2)        + sm[SB_QKV + j];
            #pragma unroll 4
            for (int j = 0; j < DIMT; j++)
                kk[j] = dot40(&sm[SW_QKV + (40+j)*DIMT], h2)   + sm[SB_QKV + 40 + j];
            #pragma unroll 4
            for (int j = 0; j < DIMT; j++)
                vv[j] = dot40(&sm[SW_QKV + (80+j)*DIMT], h2)   + sm[SB_QKV + 80 + j];
        }

        // ---- causal attention via quad shuffles (2 heads of 20) ----
        float o[DIMT];
        {
            float s0[ST], s1[ST];
            #pragma unroll
            for (int t2 = 0; t2 < ST; t2++) {
                float a = 0.f, b = 0.f;
                #pragma unroll
                for (int d = 0; d < HDm; d++) {
                    float kd = __shfl_sync(0xffffffffu, kk[d], qbase + t2, 32);
                    a += qq[d] * kd;
                }
                #pragma unroll
                for (int d = HDm; d < DIMT; d++) {
                    float kd = __shfl_sync(0xffffffffu, kk[d], qbase + t2, 32);
                    b += qq[d] * kd;
                }
                s0[t2] = a * isq;
                s1[t2] = b * isq;
            }
            float m0 = -1e30f, m1 = -1e30f;
            #pragma unroll
            for (int t2 = 0; t2 < ST; t2++) {
                if (t2 <= t) { m0 = fmaxf(m0, s0[t2]); m1 = fmaxf(m1, s1[t2]); }
            }
            float p0[ST], p1[ST], d0 = 0.f, d1 = 0.f;
            #pragma unroll
            for (int t2 = 0; t2 < ST; t2++) {
                p0[t2] = (t2 <= t) ? __expf(s0[t2] - m0) : 0.f;
                p1[t2] = (t2 <= t) ? __expf(s1[t2] - m1) : 0.f;
                d0 += p0[t2]; d1 += p1[t2];
            }
            const float i0 = 1.f / d0, i1 = 1.f / d1;
            #pragma unroll
            for (int d = 0; d < HDm; d++) {
                float a = 0.f;
                #pragma unroll
                for (int t2 = 0; t2 < ST; t2++)
                    a += p0[t2] * __shfl_sync(0xffffffffu, vv[d], qbase + t2, 32);
                o[d] = a * i0;
            }
            #pragma unroll
            for (int d = HDm; d < DIMT; d++) {
                float a = 0.f;
                #pragma unroll
                for (int t2 = 0; t2 < ST; t2++)
                    a += p1[t2] * __shfl_sync(0xffffffffu, vv[d], qbase + t2, 32);
                o[d] = a * i1;
            }
        }

        // ---- Wo projection + residual + LN1 ----
        float hc[DIMT];
        {
            u64 o2[20];
            #pragma unroll
            for (int i = 0; i < 20; i++) o2[i] = f2pack(o[2*i], o[2*i+1]);
            #pragma unroll 4
            for (int j = 0; j < DIMT; j++)
                hc[j] = h[j] + dot40(&sm[SW_O + j*DIMT], o2) + sm[SB_O + j];
        }
        {
            float mean = 0.f;
            #pragma unroll
            for (int i = 0; i < DIMT; i++) mean += hc[i];
            mean *= (1.f / DIMT);
            float var = 0.f;
            #pragma unroll
            for (int i = 0; i < DIMT; i++) { float d = hc[i] - mean; var += d * d; }
            var *= (1.f / DIMT);
            float rstd = rsqrtf(var + 1e-6f);
            #pragma unroll
            for (int i = 0; i < DIMT; i++) hc[i] = (hc[i] - mean) * rstd * sm[SG1 + i] + sm[SBT1 + i];
        }

        // ---- publish hc to smem for token-paired FFN ----
        #pragma unroll
        for (int i = 0; i < 10; i++)
            *reinterpret_cast<float4*>(&sm[hcbase + i*4]) =
                make_float4(hc[4*i], hc[4*i+1], hc[4*i+2], hc[4*i+3]);
        __syncthreads();

        // ---- FFN 40 -> 256(relu) -> 40: token-paired, k-split ----
        // thread (row rb, tp=t>>1, kh=t&1) handles tokens {2tp, 2tp+1} over k in [kh*128, kh*128+128)
        u64 fa[20];
        {
            const int tp = t >> 1, kh = t & 1;
            const int ba = SHC + (rb*4 + 2*tp) * 44;   // token 2tp
            const int bb2_ = ba + 44;                   // token 2tp+1
            u64 hpa[20], hpb[20];
            #pragma unroll
            for (int i = 0; i < 10; i++) {
                float4 va = *reinterpret_cast<const float4*>(&sm[ba  + i*4]);
                float4 vb = *reinterpret_cast<const float4*>(&sm[bb2_ + i*4]);
                hpa[2*i]   = f2pack(va.x, va.y); hpa[2*i+1] = f2pack(va.z, va.w);
                hpb[2*i]   = f2pack(vb.x, vb.y); hpb[2*i+1] = f2pack(vb.z, vb.w);
            }
            u64 faa[20], fab[20];
            #pragma unroll
            for (int j = 0; j < 20; j++) {
                u64 bz = (kh == 0) ? f2pack(sm[SFB2 + 2*j], sm[SFB2 + 2*j+1]) : 0ULL;
                faa[j] = bz; fab[j] = bz;   // bias counted once (kh==0 half only)
            }
            const int k0 = kh * 128;
            #pragma unroll 2
            for (int k = k0; k < k0 + 128; k++) {
                const ulonglong2* w1r = reinterpret_cast<const ulonglong2*>(&sm[SW1 + k*DIMT]);
                u64 A0=0,A1=0,A2=0,A3=0, B0=0,B1=0,B2=0,B3=0;
                #pragma unroll
                for (int i = 0; i < 5; i++) {
                    ulonglong2 p = w1r[2*i];
                    ulonglong2 q = w1r[2*i+1];
                    A0 = ffma2(p.x, hpa[4*i+0], A0); B0 = ffma2(p.x, hpb[4*i+0], B0);
                    A1 = ffma2(p.y, hpa[4*i+1], A1); B1 = ffma2(p.y, hpb[4*i+1], B1);
                    A2 = ffma2(q.x, hpa[4*i+2], A2); B2 = ffma2(q.x, hpb[4*i+2], B2);
                    A3 = ffma2(q.y, hpa[4*i+3], A3); B3 = ffma2(q.y, hpb[4*i+3], B3);
                }
                float l0,h0,l1,h1,l2,h2,l3,h3;
                f2unpack(A0,l0,h0); f2unpack(A1,l1,h1); f2unpack(A2,l2,h2); f2unpack(A3,l3,h3);
                float sa = ((l0+h0)+(l1+h1)) + ((l2+h2)+(l3+h3)) + sm[SFB1 + k];
                f2unpack(B0,l0,h0); f2unpack(B1,l1,h1); f2unpack(B2,l2,h2); f2unpack(B3,l3,h3);
                float sb = ((l0+h0)+(l1+h1)) + ((l2+h2)+(l3+h3)) + sm[SFB1 + k];
                sa = fmaxf(sa, 0.f); sb = fmaxf(sb, 0.f);
                u64 s2a = f2dup(sa), s2b = f2dup(sb);
                const ulonglong2* w2r = reinterpret_cast<const ulonglong2*>(&sm[SW2T + k*DIMT]);
                #pragma unroll
                for (int i = 0; i < 10; i++) {
                    ulonglong2 u = w2r[i];
                    faa[2*i]   = ffma2(u.x, s2a, faa[2*i]);
                    faa[2*i+1] = ffma2(u.y, s2a, faa[2*i+1]);
                    fab[2*i]   = ffma2(u.x, s2b, fab[2*i]);
                    fab[2*i+1] = ffma2(u.y, s2b, fab[2*i+1]);
                }
            }
            // combine with partner lane (lane^1 has same (row,tp), other k-half).
            // my own token = 2tp+kh -> slot kh is the one I keep.
            #pragma unroll
            for (int j = 0; j < 20; j++) {
                u64 send = (kh == 0) ? fab[j] : faa[j];    // the slot I don't need
                u64 recv = __shfl_xor_sync(0xffffffffu, send, 1);
                u64 mine = (kh == 0) ? faa[j] : fab[j];
                fa[j] = f2add(mine, recv);
            }
        }

        // ---- reload own hc, residual + LN2 -> h ----
        #pragma unroll
        for (int i = 0; i < 10; i++) {
            float4 v = *reinterpret_cast<const float4*>(&sm[hcbase + i*4]);
            hc[4*i] = v.x; hc[4*i+1] = v.y; hc[4*i+2] = v.z; hc[4*i+3] = v.w;
        }
        #pragma unroll
        for (int j = 0; j < 20; j++) {
            float lo, hi;
            f2unpack(fa[j], lo, hi);
            hc[2*j]   += lo;
            hc[2*j+1] += hi;
        }
        {
            float mean = 0.f;
            #pragma unroll
            for (int i = 0; i < DIMT; i++) mean += hc[i];
            mean *= (1.f / DIMT);
            float var = 0.f;
            #pragma unroll
            for (int i = 0; i < DIMT; i++) { float d = hc[i] - mean; var += d * d; }
            var *= (1.f / DIMT);
            float rstd = rsqrtf(var + 1e-6f);
            #pragma unroll
            for (int i = 0; i < DIMT; i++) h[i] = (hc[i] - mean) * rstd * sm[SG2 + i] + sm[SBT2 + i];
        }
    }

    // epilogue: feature-major h + current_obs (each thread writes its token's 40 features)
    #pragma unroll
    for (int i = 0; i < DIMT; i++)
        g_hT[(size_t)(t*DIMT + i) * RTOT + r] = h[i];
    {
        const float* orow = obs + (size_t)r * OBSD + 160 + t * 8;
        #pragma unroll
        for (int j = 0; j < 8; j++)
            g_hT[(size_t)(160 + t*8 + j) * RTOT + r] = orow[j];
    }
}

// ---------------- fused dense chain: emb1 -> relu -> emb2 -> relu -> xl, xr ----------------
// Block-GEMM: 128 rows x 128 outs per block, thread tile 8x8.
// Columns XOR-swizzled by k-row to kill the 16-way bank conflicts of out-major
// access (stride 132 ≡ 4 mod 32 made tc*8*132 ≡ 0 mod 128B for all lanes).
#define DS_STRIDE 132
#define DSA 0                          // A^T buffer: K x 132 (K up to 192)
#define DSB (192*DS_STRIDE)            // B buffer:   K x 132
#define SM_D (2*192*DS_STRIDE)         // 50688 floats -> 202,752 bytes
// swizzle: permute 16B groups of the column by bits [3:6) of the k-row
#define DSWZ(k, col) ((col) ^ ((((k) >> 3) & 7) << 2))

template<int K>
__device__ __forceinline__ void dgemm_phase(const float* __restrict__ sm,
                                            int tr, int tc,
                                            const float* __restrict__ bias,
                                            u64* acc)
{
    #pragma unroll
    for (int p = 0; p < 4; p++) {
        u64 bp = f2pack(bias[tc*8 + 2*p], bias[tc*8 + 2*p + 1]);
        #pragma unroll
        for (int r = 0; r < 8; r++) acc[r*4 + p] = bp;
    }
    #pragma unroll 4
    for (int k = 0; k < K; k++) {
        float4 a0 = *reinterpret_cast<const float4*>(&sm[DSA + k*DS_STRIDE + DSWZ(k, tr*8)]);
        float4 a1 = *reinterpret_cast<const float4*>(&sm[DSA + k*DS_STRIDE + DSWZ(k, tr*8 + 4)]);
        ulonglong2 b01 = *reinterpret_cast<const ulonglong2*>(&sm[DSB + k*DS_STRIDE + DSWZ(k, tc*8)]);
        ulonglong2 b23 = *reinterpret_cast<const ulonglong2*>(&sm[DSB + k*DS_STRIDE + DSWZ(k, tc*8 + 4)]);
        u64 ad[8];
        ad[0]=f2dup(a0.x); ad[1]=f2dup(a0.y); ad[2]=f2dup(a0.z); ad[3]=f2dup(a0.w);
        ad[4]=f2dup(a1.x); ad[5]=f2dup(a1.y); ad[6]=f2dup(a1.z); ad[7]=f2dup(a1.w);
        #pragma unroll
        for (int rr = 0; rr < 8; rr++) {
            acc[rr*4+0] = ffma2(ad[rr], b01.x, acc[rr*4+0]);
            acc[rr*4+1] = ffma2(ad[rr], b01.y, acc[rr*4+1]);
            acc[rr*4+2] = ffma2(ad[rr], b23.x, acc[rr*4+2]);
            acc[rr*4+3] = ffma2(ad[rr], b23.y, acc[rr*4+3]);
        }
    }
}

// relu + write acc as transposed activations into DSA (next phase's A^T)
__device__ __forceinline__ void store_act(float* __restrict__ sm, int tr, int tc, const u64* acc)
{
    #pragma unroll
    for (int rr = 0; rr < 8; rr++) {
        #pragma unroll
        for (int p = 0; p < 4; p++) {
            float lo, hi;
            f2unpack(acc[rr*4+p], lo, hi);
            lo = fmaxf(lo, 0.f); hi = fmaxf(hi, 0.f);
            int k0 = tc*8 + 2*p;
            sm[DSA + (k0    )*DS_STRIDE + DSWZ(k0,     tr*8 + rr)] = lo;
            sm[DSA + (k0 + 1)*DS_STRIDE + DSWZ(k0 + 1, tr*8 + rr)] = hi;
        }
    }
}

// stage a 128x128 weight matrix W[j][k] into DSB as B[k][j] (swizzled)
__device__ __forceinline__ void stage_b128(float* __restrict__ sm, const float* __restrict__ W, int tid)
{
    for (int v = tid; v < 128*32; v += 256) {
        int j = v >> 5, k0 = (v & 31) * 4;
        float4 w = *reinterpret_cast<const float4*>(&W[j*128 + k0]);
        sm[DSB + (k0+0)*DS_STRIDE + DSWZ(k0+0, j)] = w.x;
        sm[DSB + (k0+1)*DS_STRIDE + DSWZ(k0+1, j)] = w.y;
        sm[DSB + (k0+2)*DS_STRIDE + DSWZ(k0+2, j)] = w.z;
        sm[DSB + (k0+3)*DS_STRIDE + DSWZ(k0+3, j)] = w.w;
    }
}

__global__ void __launch_bounds__(256, 1)
kdense(const float* __restrict__ W1, const float* __restrict__ b1,
       const float* __restrict__ W2, const float* __restrict__ b2,
       const float* __restrict__ wl, const float* __restrict__ bl,
       const float* __restrict__ wr, const float* __restrict__ br)
{
    extern __shared__ float sm[];
    const int tid = threadIdx.x;
    const int tr = tid >> 4;       // row group 0..15
    const int tc = tid & 15;       // out group 0..15
    const int r0 = blockIdx.x * 128;

    // stage phase-1 A^T (g_hT is feature-major => direct) and B = W1^T (W1 is [128][192])
    for (int v = tid; v < 192*32; v += 256) {
        int f = v >> 5, c = v & 31;
        *reinterpret_cast<float4*>(&sm[DSA + f*DS_STRIDE + DSWZ(f, c*4)]) =
            *reinterpret_cast<const float4*>(&g_hT[(size_t)f * RTOT + r0 + c*4]);
    }
    for (int v = tid; v < 128*48; v += 256) {
        int j = v / 48, k0 = (v % 48) * 4;
        float4 w = *reinterpret_cast<const float4*>(&W1[j*192 + k0]);
        sm[DSB + (k0+0)*DS_STRIDE + DSWZ(k0+0, j)] = w.x;
        sm[DSB + (k0+1)*DS_STRIDE + DSWZ(k0+1, j)] = w.y;
        sm[DSB + (k0+2)*DS_STRIDE + DSWZ(k0+2, j)] = w.z;
        sm[DSB + (k0+3)*DS_STRIDE + DSWZ(k0+3, j)] = w.w;
    }
    __syncthreads();

    u64 acc[32];

    // phase 1: l1 = relu(ret @ W1^T + b1), K=192
    dgemm_phase<192>(sm, tr, tc, b1, acc);
    __syncthreads();                    // all reads of A/B done
    store_act(sm, tr, tc, acc);         // DSA <- l1^T (with relu)
    stage_b128(sm, W2, tid);            // DSB <- W2^T
    __syncthreads();

    // phase 2: l2 = relu(l1 @ W2^T + b2), K=128
    dgemm_phase<128>(sm, tr, tc, b2, acc);
    __syncthreads();
    store_act(sm, tr, tc, acc);         // DSA <- emb^T (with relu)
    stage_b128(sm, wl, tid);            // DSB <- WL^T
    __syncthreads();

    // phase 3: xl = emb @ WL^T + bl (no relu)
    dgemm_phase<128>(sm, tr, tc, bl, acc);
    #pragma unroll
    for (int rr = 0; rr < 8; rr++) {
        float o0,o1,o2,o3,o4,o5,o6,o7;
        f2unpack(acc[rr*4+0], o0, o1);
        f2unpack(acc[rr*4+1], o2, o3);
        f2unpack(acc[rr*4+2], o4, o5);
        f2unpack(acc[rr*4+3], o6, o7);
        size_t row = (size_t)(r0 + tr*8 + rr);
        *reinterpret_cast<float4*>(&g_xl[row*HIDD + tc*8    ]) = make_float4(o0,o1,o2,o3);
        *reinterpret_cast<float4*>(&g_xl[row*HIDD + tc*8 + 4]) = make_float4(o4,o5,o6,o7);
    }
    __syncthreads();                    // WL reads done
    stage_b128(sm, wr, tid);            // DSB <- WR^T
    __syncthreads();

    // phase 4: xr = emb @ WR^T + br (no relu)
    dgemm_phase<128>(sm, tr, tc, br, acc);
    #pragma unroll
    for (int rr = 0; rr < 8; rr++) {
        float o0,o1,o2,o3,o4,o5,o6,o7;
        f2unpack(acc[rr*4+0], o0, o1);
        f2unpack(acc[rr*4+1], o2, o3);
        f2unpack(acc[rr*4+2], o4, o5);
        f2unpack(acc[rr*4+3], o6, o7);
        size_t row = (size_t)(r0 + tr*8 + rr);
        *reinterpret_cast<float4*>(&g_xr[row*HIDD + tc*8    ]) = make_float4(o0,o1,o2,o3);
        *reinterpret_cast<float4*>(&g_xr[row*HIDD + tc*8 + 4]) = make_float4(o4,o5,o6,o7);
    }
}

// ---------------- GAT aggregation + final head (warp per node, no atomics) ----------------
__global__ void __launch_bounds__(256)
kgat(const float* __restrict__ att, const float* __restrict__ gbias,
     const float* __restrict__ Wq,  const float* __restrict__ bq,
     float* __restrict__ out)
{
    const int wid  = (blockIdx.x * 256 + threadIdx.x) >> 5;
    const int lane = threadIdx.x & 31;
    const int r = wid;
    const int b = r >> 10;      // / NN
    const int n = r & 1023;     // % NN

    const float4 xr4 = *reinterpret_cast<const float4*>(&g_xr[(size_t)r * HIDD + lane*4]);
    const float4 av  = *reinterpret_cast<const float4*>(&att[lane*4]);

    float4 acc = make_float4(0.f, 0.f, 0.f, 0.f);
    float den = 0.f;

    const int beg = g_off[n];
    const int end = g_off[n + 1];

    for (int idx = beg - 1; idx < end; idx++) {
        int src = (idx < beg) ? r : (g_srcs[idx] + (b << 10));   // first iteration = self loop
        const float4 xs = *reinterpret_cast<const float4*>(&g_xl[(size_t)src * HIDD + lane*4]);
        float4 m;
        m.x = xs.x + xr4.x; m.x = (m.x >= 0.f) ? m.x : 0.2f * m.x;
        m.y = xs.y + xr4.y; m.y = (m.y >= 0.f) ? m.y : 0.2f * m.y;
        m.z = xs.z + xr4.z; m.z = (m.z >= 0.f) ? m.z : 0.2f * m.z;
        m.w = xs.w + xr4.w; m.w = (m.w >= 0.f) ? m.w : 0.2f * m.w;
        float p = m.x*av.x + m.y*av.y + m.z*av.z + m.w*av.w;
        // reduce within 8-lane head group (lanes 8h..8h+7 hold head h)
        p += __shfl_xor_sync(0xffffffffu, p, 1);
        p += __shfl_xor_sync(0xffffffffu, p, 2);
        p += __shfl_xor_sync(0xffffffffu, p, 4);
        float wgt = __expf(p);   // scores tiny; softmax shift-invariant -> skip segment_max
        den += wgt;
        acc.x += wgt * xs.x;
        acc.y += wgt * xs.y;
        acc.z += wgt * xs.z;
        acc.w += wgt * xs.w;
    }

    const float4 gb = *reinterpret_cast<const float4*>(&gbias[lane*4]);
    const float invd = 1.f / den;
    float4 h2;
    h2.x = acc.x * invd + gb.x;
    h2.y = acc.y * invd + gb.y;
    h2.z = acc.z * invd + gb.z;
    h2.w = acc.w * invd + gb.w;

    float my = 0.f;
    #pragma unroll
    for (int j = 0; j < 8; j++) {
        const float4 wq = *reinterpret_cast<const float4*>(&Wq[j*HIDD + lane*4]);
        float p = wq.x*h2.x + wq.y*h2.y + wq.z*h2.z + wq.w*h2.w;
        p += __shfl_xor_sync(0xffffffffu, p, 16);
        p += __shfl_xor_sync(0xffffffffu, p, 8);
        p += __shfl_xor_sync(0xffffffffu, p, 4);
        p += __shfl_xor_sync(0xffffffffu, p, 2);
        p += __shfl_xor_sync(0xffffffffu, p, 1);
        if (lane == j) my = p + bq[j];
    }
    if (lane < 8) out[(size_t)r * 8 + lane] = my;
}

// ---------------- launch ----------------
extern "C" void kernel_launch(void* const* d_in, const int* in_sizes, int n_in,
                              void* d_out, int out_size)
{
    const float* obs      = (const float*)d_in[0];
    const int*   ei       = (const int*)  d_in[1];
    const float* W_emb1   = (const float*)d_in[2];
    const float* b_emb1   = (const float*)d_in[3];
    const float* W_emb2   = (const float*)d_in[4];
    const float* b_emb2   = (const float*)d_in[5];
    const float* tf_wqkv  = (const float*)d_in[6];
    const float* tf_bqkv  = (const float*)d_in[7];
    const float* tf_wo    = (const float*)d_in[8];
    const float* tf_bo    = (const float*)d_in[9];
    const float* ffn_w1   = (const float*)d_in[10];
    const float* ffn_b1   = (const float*)d_in[11];
    const float* ffn_w2   = (const float*)d_in[12];
    const float* ffn_b2   = (const float*)d_in[13];
    const float* ln1_g    = (const float*)d_in[14];
    const float* ln1_b    = (const float*)d_in[15];
    const float* ln2_g    = (const float*)d_in[16];
    const float* ln2_b    = (const float*)d_in[17];
    const float* gat_wl   = (const float*)d_in[18];
    const float* gat_bl   = (const float*)d_in[19];
    const float* gat_wr   = (const float*)d_in[20];
    const float* gat_br   = (const float*)d_in[21];
    const float* gat_att  = (const float*)d_in[22];
    const float* gat_bias = (const float*)d_in[23];
    const float* W_q      = (const float*)d_in[24];
    const float* b_q      = (const float*)d_in[25];
    const float* pe       = (const float*)d_in[26];

    cudaFuncSetAttribute(kt_kernel, cudaFuncAttributeMaxDynamicSharedMemorySize, SM_KT * 4);
    cudaFuncSetAttribute(kdense,    cudaFuncAttributeMaxDynamicSharedMemorySize, SM_D * 4);

    kcsr<<<1, 256>>>(ei);
    kt_kernel<<<RTOT / 64, 256, SM_KT * 4>>>(obs,
        tf_wqkv, tf_bqkv, tf_wo, tf_bo,
        ffn_w1, ffn_b1, ffn_w2, ffn_b2,
        ln1_g, ln1_b, ln2_g, ln2_b, pe);
    kdense<<<RTOT / 128, 256, SM_D * 4>>>(W_emb1, b_emb1, W_emb2, b_emb2,
                                          gat_wl, gat_bl, gat_wr, gat_br);
    kgat<<<(RTOT * 32) / 256, 256>>>(gat_att, gat_bias, W_q, b_q, (float*)d_out);
}

// round 17
// speedup vs baseline: 1.1809x; 1.0732x over previous
#include <cuda_runtime.h>
#include <math.h>

// ---------------- problem constants ----------------
#define RB    128
#define NN    1024
#define RTOT  (RB*NN)        // 131072 rows
#define DIMT  40
#define ST    4              // seq len (HIST-1)
#define HDm   20             // head dim
#define FFND  256
#define HIDD  128
#define ED    4096
#define OBSD  200
#define RETD  192            // S*DIM + 32

typedef unsigned long long u64;

// ---------------- f32x2 packed helpers ----------------
__device__ __forceinline__ u64 f2pack(float lo, float hi) {
    u64 r; asm("mov.b64 %0,{%1,%2};" : "=l"(r) : "f"(lo), "f"(hi)); return r;
}
__device__ __forceinline__ void f2unpack(u64 v, float& lo, float& hi) {
    asm("mov.b64 {%0,%1},%2;" : "=f"(lo), "=f"(hi) : "l"(v));
}
__device__ __forceinline__ u64 f2dup(float x) { return f2pack(x, x); }
__device__ __forceinline__ u64 ffma2(u64 a, u64 b, u64 c) {
    u64 d; asm("fma.rn.f32x2 %0,%1,%2,%3;" : "=l"(d) : "l"(a), "l"(b), "l"(c)); return d;
}

// dot of a 40-float smem row with packed x2[20] (pairs along input dim)
__device__ __forceinline__ float dot40(const float* __restrict__ wrow, const u64* __restrict__ x2) {
    const ulonglong2* w = reinterpret_cast<const ulonglong2*>(wrow);
    u64 a0 = 0ULL, a1 = 0ULL, a2 = 0ULL, a3 = 0ULL;
    #pragma unroll
    for (int i = 0; i < 5; i++) {
        ulonglong2 p = w[2*i];
        ulonglong2 q = w[2*i+1];
        a0 = ffma2(p.x, x2[4*i+0], a0);
        a1 = ffma2(p.y, x2[4*i+1], a1);
        a2 = ffma2(q.x, x2[4*i+2], a2);
        a3 = ffma2(q.y, x2[4*i+3], a3);
    }
    float l0,h0,l1,h1,l2,h2,l3,h3;
    f2unpack(a0,l0,h0); f2unpack(a1,l1,h1); f2unpack(a2,l2,h2); f2unpack(a3,l3,h3);
    return ((l0+h0)+(l1+h1)) + ((l2+h2)+(l3+h3));
}

// ---------------- device workspaces (no cudaMalloc allowed) ----------------
__device__ float g_hT[(size_t)RETD * RTOT];    // feature-major: 0..159 = h, 160..191 = current_obs
__device__ float g_xl[(size_t)RTOT * HIDD];    // row-major (edge gather)
__device__ float g_xr[(size_t)RTOT * HIDD];
__device__ int   g_off[NN + 1];
__device__ int   g_srcs[ED];

// ---------------- CSR build (single block; same base graph for all batches) ----------------
__global__ void kcsr(const int* __restrict__ ei)
{
    __shared__ int cnt[NN];
    __shared__ int head[NN];
    const int tid = threadIdx.x;
    for (int i = tid; i < NN; i += blockDim.x) cnt[i] = 0;
    __syncthreads();
    for (int e = tid; e < ED; e += blockDim.x) atomicAdd(&cnt[ei[ED + e]], 1);
    __syncthreads();
    if (tid == 0) {
        int s = 0;
        for (int n = 0; n < NN; n++) { g_off[n] = s; head[n] = s; s += cnt[n]; }
        g_off[NN] = s;
    }
    __syncthreads();
    for (int e = tid; e < ED; e += blockDim.x) {
        int d = ei[ED + e];
        int pos = atomicAdd(&head[d], 1);
        g_srcs[pos] = ei[e];
    }
}

// ---------------- transformer kernel: smem layout (float offsets) ----------------
// No hc buffer: smem = weights only -> 110,624 bytes, 2 blocks/SM.
#define SW_QKV 0
#define SB_QKV 4800
#define SW_O   4920
#define SB_O   6520
#define SG1    6560
#define SBT1   6600
#define SG2    6640
#define SBT2   6680
#define SW1    6720
#define SFB1   16960
#define SW2T   17216
#define SFB2   27456
#define SPE    27496
#define SM_KT  27656   // floats -> 110,624 bytes

// 256 threads = 64 rows x 4 tokens, 2 blocks/SM (register-dieted streaming design).
__global__ void __launch_bounds__(256, 2)
kt_kernel(const float* __restrict__ obs,
          const float* __restrict__ wqkv, const float* __restrict__ bqkv,
          const float* __restrict__ wo,   const float* __restrict__ bo,
          const float* __restrict__ w1,   const float* __restrict__ b1f,
          const float* __restrict__ w2,   const float* __restrict__ b2f,
          const float* __restrict__ g1,   const float* __restrict__ bb1,
          const float* __restrict__ g2,   const float* __restrict__ bb2,
          const float* __restrict__ pe)
{
    extern __shared__ float sm[];
    const int tid  = threadIdx.x;
    const int rb   = tid >> 2;         // row within block (0..63)
    const int t    = tid & 3;          // token (0..3)
    const int r    = blockIdx.x * 64 + rb;
    const unsigned lane  = tid & 31;
    const unsigned qbase = lane & ~3u; // first lane of my token quad

    for (int i = tid; i < ST * DIMT; i += 256) sm[SPE + i] = pe[i];
    __syncthreads();

    // my token's h = obs[r, t, :] + pe[t], kept PACKED in h2[20]
    u64 h2[20];
    {
        const float4* orow = reinterpret_cast<const float4*>(obs + (size_t)r * OBSD + t * DIMT);
        #pragma unroll
        for (int i4 = 0; i4 < 10; i4++) {
            float4 v = orow[i4];
            h2[2*i4]   = f2pack(v.x + sm[SPE + t*DIMT + i4*4+0], v.y + sm[SPE + t*DIMT + i4*4+1]);
            h2[2*i4+1] = f2pack(v.z + sm[SPE + t*DIMT + i4*4+2], v.w + sm[SPE + t*DIMT + i4*4+3]);
        }
    }

    const float isq = 0.223606797749979f;  // 1/sqrt(20)

    for (int l = 0; l < 3; l++) {
        __syncthreads();   // previous layer done reading weights
        {
            const float* p;
            p = wqkv + l*4800;  for (int i = tid; i < 4800;  i += 256) sm[SW_QKV+i] = p[i];
            p = bqkv + l*120;   for (int i = tid; i < 120;   i += 256) sm[SB_QKV+i] = p[i];
            p = wo   + l*1600;  for (int i = tid; i < 1600;  i += 256) sm[SW_O+i]   = p[i];
            p = bo   + l*40;    for (int i = tid; i < 40;    i += 256) sm[SB_O+i]   = p[i];
            p = g1   + l*40;    for (int i = tid; i < 40;    i += 256) sm[SG1+i]    = p[i];
            p = bb1  + l*40;    for (int i = tid; i < 40;    i += 256) sm[SBT1+i]   = p[i];
            p = g2   + l*40;    for (int i = tid; i < 40;    i += 256) sm[SG2+i]    = p[i];
            p = bb2  + l*40;    for (int i = tid; i < 40;    i += 256) sm[SBT2+i]   = p[i];
            p = w1   + l*10240; for (int i = tid; i < 10240; i += 256) sm[SW1+i]    = p[i];
            p = b1f  + l*256;   for (int i = tid; i < 256;   i += 256) sm[SFB1+i]   = p[i];
            p = w2   + l*10240; // transpose ffn_w2 (40x256) -> w2T[k][j]
            for (int i = tid; i < 10240; i += 256) { int j = i / 256, k = i % 256; sm[SW2T + k*DIMT + j] = p[i]; }
            p = b2f  + l*40;    for (int i = tid; i < 40;    i += 256) sm[SFB2+i]   = p[i];
        }
        __syncthreads();

        // ---- K for my token ----
        float kk[DIMT];
        #pragma unroll 4
        for (int j = 0; j < DIMT; j++)
            kk[j] = dot40(&sm[SW_QKV + (40+j)*DIMT], h2) + sm[SB_QKV + 40 + j];

        // ---- stream Q into scores (q never stored) ----
        float s0[ST] = {0.f,0.f,0.f,0.f};
        float s1[ST] = {0.f,0.f,0.f,0.f};
        #pragma unroll 4
        for (int j = 0; j < DIMT; j++) {
            float qj = dot40(&sm[SW_QKV + j*DIMT], h2) + sm[SB_QKV + j];
            #pragma unroll
            for (int t2 = 0; t2 < ST; t2++) {
                float kd = __shfl_sync(0xffffffffu, kk[j], qbase + t2, 32);
                if (j < HDm) s0[t2] += qj * kd; else s1[t2] += qj * kd;
            }
        }

        // ---- causal softmax per head, inv folded into p ----
        float p0[ST], p1[ST];
        {
            float m0 = -1e30f, m1 = -1e30f;
            #pragma unroll
            for (int t2 = 0; t2 < ST; t2++) {
                s0[t2] *= isq; s1[t2] *= isq;
                if (t2 <= t) { m0 = fmaxf(m0, s0[t2]); m1 = fmaxf(m1, s1[t2]); }
            }
            float d0 = 0.f, d1 = 0.f;
            #pragma unroll
            for (int t2 = 0; t2 < ST; t2++) {
                p0[t2] = (t2 <= t) ? __expf(s0[t2] - m0) : 0.f;
                p1[t2] = (t2 <= t) ? __expf(s1[t2] - m1) : 0.f;
                d0 += p0[t2]; d1 += p1[t2];
            }
            const float i0 = 1.f / d0, i1 = 1.f / d1;
            #pragma unroll
            for (int t2 = 0; t2 < ST; t2++) { p0[t2] *= i0; p1[t2] *= i1; }
        }

        // ---- stream V directly into packed attention output o2 ----
        u64 o2[20];
        #pragma unroll 2
        for (int jp = 0; jp < 20; jp++) {
            const int j0 = 2*jp, j1 = 2*jp + 1;   // same head (boundary at 20 is even)
            float v0 = dot40(&sm[SW_QKV + (80+j0)*DIMT], h2) + sm[SB_QKV + 80 + j0];
            float v1 = dot40(&sm[SW_QKV + (80+j1)*DIMT], h2) + sm[SB_QKV + 80 + j1];
            float a0 = 0.f, a1 = 0.f;
            #pragma unroll
            for (int t2 = 0; t2 < ST; t2++) {
                float pw = (j0 < HDm) ? p0[t2] : p1[t2];
                a0 += pw * __shfl_sync(0xffffffffu, v0, qbase + t2, 32);
                a1 += pw * __shfl_sync(0xffffffffu, v1, qbase + t2, 32);
            }
            o2[jp] = f2pack(a0, a1);
        }

        // ---- Wo projection + residual, written in place into h2 ----
        #pragma unroll 2
        for (int jp = 0; jp < 20; jp++) {
            float hlo, hhi;
            f2unpack(h2[jp], hlo, hhi);
            hlo += dot40(&sm[SW_O + (2*jp  )*DIMT], o2) + sm[SB_O + 2*jp];
            hhi += dot40(&sm[SW_O + (2*jp+1)*DIMT], o2) + sm[SB_O + 2*jp+1];
            h2[jp] = f2pack(hlo, hhi);
        }
        // ---- LN1 in place on h2 ----
        {
            float mean = 0.f;
            #pragma unroll
            for (int jp = 0; jp < 20; jp++) { float a,b; f2unpack(h2[jp],a,b); mean += a + b; }
            mean *= (1.f / DIMT);
            float var = 0.f;
            #pragma unroll
            for (int jp = 0; jp < 20; jp++) {
                float a,b; f2unpack(h2[jp],a,b);
                float da = a - mean, db = b - mean; var += da*da + db*db;
            }
            var *= (1.f / DIMT);
            float rstd = rsqrtf(var + 1e-6f);
            #pragma unroll
            for (int jp = 0; jp < 20; jp++) {
                float a,b; f2unpack(h2[jp],a,b);
                a = (a - mean) * rstd * sm[SG1 + 2*jp]   + sm[SBT1 + 2*jp];
                b = (b - mean) * rstd * sm[SG1 + 2*jp+1] + sm[SBT1 + 2*jp+1];
                h2[jp] = f2pack(a, b);
            }
        }

        // ---- FFN 40 -> 256(relu) -> 40, unpaired (h2 is the input, fa accumulates) ----
        u64 fa[20];
        #pragma unroll
        for (int jp = 0; jp < 20; jp++) fa[jp] = f2pack(sm[SFB2 + 2*jp], sm[SFB2 + 2*jp+1]);
        #pragma unroll 2
        for (int k = 0; k < FFND; k++) {
            float s = dot40(&sm[SW1 + k*DIMT], h2) + sm[SFB1 + k];
            s = fmaxf(s, 0.f);
            u64 s2 = f2dup(s);
            const ulonglong2* w2r = reinterpret_cast<const ulonglong2*>(&sm[SW2T + k*DIMT]);
            #pragma unroll
            for (int i = 0; i < 10; i++) {
                ulonglong2 u = w2r[i];
                fa[2*i]   = ffma2(u.x, s2, fa[2*i]);
                fa[2*i+1] = ffma2(u.y, s2, fa[2*i+1]);
            }
        }

        // ---- residual + LN2 in place -> h2 ----
        {
            float mean = 0.f;
            #pragma unroll
            for (int jp = 0; jp < 20; jp++) {
                float a,b, fa0,fa1;
                f2unpack(h2[jp], a, b);
                f2unpack(fa[jp], fa0, fa1);
                a += fa0; b += fa1;
                h2[jp] = f2pack(a, b);
                mean += a + b;
            }
            mean *= (1.f / DIMT);
            float var = 0.f;
            #pragma unroll
            for (int jp = 0; jp < 20; jp++) {
                float a,b; f2unpack(h2[jp],a,b);
                float da = a - mean, db = b - mean; var += da*da + db*db;
            }
            var *= (1.f / DIMT);
            float rstd = rsqrtf(var + 1e-6f);
            #pragma unroll
            for (int jp = 0; jp < 20; jp++) {
                float a,b; f2unpack(h2[jp],a,b);
                a = (a - mean) * rstd * sm[SG2 + 2*jp]   + sm[SBT2 + 2*jp];
                b = (b - mean) * rstd * sm[SG2 + 2*jp+1] + sm[SBT2 + 2*jp+1];
                h2[jp] = f2pack(a, b);
            }
        }
    }

    // epilogue: feature-major h + current_obs
    #pragma unroll
    for (int jp = 0; jp < 20; jp++) {
        float a,b; f2unpack(h2[jp],a,b);
        g_hT[(size_t)(t*DIMT + 2*jp    ) * RTOT + r] = a;
        g_hT[(size_t)(t*DIMT + 2*jp + 1) * RTOT + r] = b;
    }
    {
        const float* orow = obs + (size_t)r * OBSD + 160 + t * 8;
        #pragma unroll
        for (int j = 0; j < 8; j++)
            g_hT[(size_t)(160 + t*8 + j) * RTOT + r] = orow[j];
    }
}

// ---------------- fused dense chain: emb1 -> relu -> emb2 -> relu -> xl, xr ----------------
#define DS_STRIDE 132
#define DSA 0
#define DSB (192*DS_STRIDE)
#define SM_D (2*192*DS_STRIDE)
#define DSWZ(k, col) ((col) ^ ((((k) >> 3) & 7) << 2))

template<int K>
__device__ __forceinline__ void dgemm_phase(const float* __restrict__ sm,
                                            int tr, int tc,
                                            const float* __restrict__ bias,
                                            u64* acc)
{
    #pragma unroll
    for (int p = 0; p < 4; p++) {
        u64 bp = f2pack(bias[tc*8 + 2*p], bias[tc*8 + 2*p + 1]);
        #pragma unroll
        for (int r = 0; r < 8; r++) acc[r*4 + p] = bp;
    }
    #pragma unroll 4
    for (int k = 0; k < K; k++) {
        float4 a0 = *reinterpret_cast<const float4*>(&sm[DSA + k*DS_STRIDE + DSWZ(k, tr*8)]);
        float4 a1 = *reinterpret_cast<const float4*>(&sm[DSA + k*DS_STRIDE + DSWZ(k, tr*8 + 4)]);
        ulonglong2 b01 = *reinterpret_cast<const ulonglong2*>(&sm[DSB + k*DS_STRIDE + DSWZ(k, tc*8)]);
        ulonglong2 b23 = *reinterpret_cast<const ulonglong2*>(&sm[DSB + k*DS_STRIDE + DSWZ(k, tc*8 + 4)]);
        u64 ad[8];
        ad[0]=f2dup(a0.x); ad[1]=f2dup(a0.y); ad[2]=f2dup(a0.z); ad[3]=f2dup(a0.w);
        ad[4]=f2dup(a1.x); ad[5]=f2dup(a1.y); ad[6]=f2dup(a1.z); ad[7]=f2dup(a1.w);
        #pragma unroll
        for (int rr = 0; rr < 8; rr++) {
            acc[rr*4+0] = ffma2(ad[rr], b01.x, acc[rr*4+0]);
            acc[rr*4+1] = ffma2(ad[rr], b01.y, acc[rr*4+1]);
            acc[rr*4+2] = ffma2(ad[rr], b23.x, acc[rr*4+2]);
            acc[rr*4+3] = ffma2(ad[rr], b23.y, acc[rr*4+3]);
        }
    }
}

__device__ __forceinline__ void store_act(float* __restrict__ sm, int tr, int tc, const u64* acc)
{
    #pragma unroll
    for (int rr = 0; rr < 8; rr++) {
        #pragma unroll
        for (int p = 0; p < 4; p++) {
            float lo, hi;
            f2unpack(acc[rr*4+p], lo, hi);
            lo = fmaxf(lo, 0.f); hi = fmaxf(hi, 0.f);
            int k0 = tc*8 + 2*p;
            sm[DSA + (k0    )*DS_STRIDE + DSWZ(k0,     tr*8 + rr)] = lo;
            sm[DSA + (k0 + 1)*DS_STRIDE + DSWZ(k0 + 1, tr*8 + rr)] = hi;
        }
    }
}

__device__ __forceinline__ void stage_b128(float* __restrict__ sm, const float* __restrict__ W, int tid)
{
    for (int v = tid; v < 128*32; v += 256) {
        int j = v >> 5, k0 = (v & 31) * 4;
        float4 w = *reinterpret_cast<const float4*>(&W[j*128 + k0]);
        sm[DSB + (k0+0)*DS_STRIDE + DSWZ(k0+0, j)] = w.x;
        sm[DSB + (k0+1)*DS_STRIDE + DSWZ(k0+1, j)] = w.y;
        sm[DSB + (k0+2)*DS_STRIDE + DSWZ(k0+2, j)] = w.z;
        sm[DSB + (k0+3)*DS_STRIDE + DSWZ(k0+3, j)] = w.w;
    }
}

__global__ void __launch_bounds__(256, 1)
kdense(const float* __restrict__ W1, const float* __restrict__ b1,
       const float* __restrict__ W2, const float* __restrict__ b2,
       const float* __restrict__ wl, const float* __restrict__ bl,
       const float* __restrict__ wr, const float* __restrict__ br)
{
    extern __shared__ float sm[];
    const int tid = threadIdx.x;
    const int tr = tid >> 4;
    const int tc = tid & 15;
    const int r0 = blockIdx.x * 128;

    for (int v = tid; v < 192*32; v += 256) {
        int f = v >> 5, c = v & 31;
        *reinterpret_cast<float4*>(&sm[DSA + f*DS_STRIDE + DSWZ(f, c*4)]) =
            *reinterpret_cast<const float4*>(&g_hT[(size_t)f * RTOT + r0 + c*4]);
    }
    for (int v = tid; v < 128*48; v += 256) {
        int j = v / 48, k0 = (v % 48) * 4;
        float4 w = *reinterpret_cast<const float4*>(&W1[j*192 + k0]);
        sm[DSB + (k0+0)*DS_STRIDE + DSWZ(k0+0, j)] = w.x;
        sm[DSB + (k0+1)*DS_STRIDE + DSWZ(k0+1, j)] = w.y;
        sm[DSB + (k0+2)*DS_STRIDE + DSWZ(k0+2, j)] = w.z;
        sm[DSB + (k0+3)*DS_STRIDE + DSWZ(k0+3, j)] = w.w;
    }
    __syncthreads();

    u64 acc[32];

    dgemm_phase<192>(sm, tr, tc, b1, acc);
    __syncthreads();
    store_act(sm, tr, tc, acc);
    stage_b128(sm, W2, tid);
    __syncthreads();

    dgemm_phase<128>(sm, tr, tc, b2, acc);
    __syncthreads();
    store_act(sm, tr, tc, acc);
    stage_b128(sm, wl, tid);
    __syncthreads();

    dgemm_phase<128>(sm, tr, tc, bl, acc);
    #pragma unroll
    for (int rr = 0; rr < 8; rr++) {
        float o0,o1,o2,o3,o4,o5,o6,o7;
        f2unpack(acc[rr*4+0], o0, o1);
        f2unpack(acc[rr*4+1], o2, o3);
        f2unpack(acc[rr*4+2], o4, o5);
        f2unpack(acc[rr*4+3], o6, o7);
        size_t row = (size_t)(r0 + tr*8 + rr);
        *reinterpret_cast<float4*>(&g_xl[row*HIDD + tc*8    ]) = make_float4(o0,o1,o2,o3);
        *reinterpret_cast<float4*>(&g_xl[row*HIDD + tc*8 + 4]) = make_float4(o4,o5,o6,o7);
    }
    __syncthreads();
    stage_b128(sm, wr, tid);
    __syncthreads();

    dgemm_phase<128>(sm, tr, tc, br, acc);
    #pragma unroll
    for (int rr = 0; rr < 8; rr++) {
        float o0,o1,o2,o3,o4,o5,o6,o7;
        f2unpack(acc[rr*4+0], o0, o1);
        f2unpack(acc[rr*4+1], o2, o3);
        f2unpack(acc[rr*4+2], o4, o5);
        f2unpack(acc[rr*4+3], o6, o7);
        size_t row = (size_t)(r0 + tr*8 + rr);
        *reinterpret_cast<float4*>(&g_xr[row*HIDD + tc*8    ]) = make_float4(o0,o1,o2,o3);
        *reinterpret_cast<float4*>(&g_xr[row*HIDD + tc*8 + 4]) = make_float4(o4,o5,o6,o7);
    }
}

// ---------------- GAT aggregation + final head (warp per node, no atomics) ----------------
__global__ void __launch_bounds__(256)
kgat(const float* __restrict__ att, const float* __restrict__ gbias,
     const float* __restrict__ Wq,  const float* __restrict__ bq,
     float* __restrict__ out)
{
    const int wid  = (blockIdx.x * 256 + threadIdx.x) >> 5;
    const int lane = threadIdx.x & 31;
    const int r = wid;
    const int b = r >> 10;
    const int n = r & 1023;

    const float4 xr4 = *reinterpret_cast<const float4*>(&g_xr[(size_t)r * HIDD + lane*4]);
    const float4 av  = *reinterpret_cast<const float4*>(&att[lane*4]);

    float4 acc = make_float4(0.f, 0.f, 0.f, 0.f);
    float den = 0.f;

    const int beg = g_off[n];
    const int end = g_off[n + 1];

    for (int idx = beg - 1; idx < end; idx++) {
        int src = (idx < beg) ? r : (g_srcs[idx] + (b << 10));
        const float4 xs = *reinterpret_cast<const float4*>(&g_xl[(size_t)src * HIDD + lane*4]);
        float4 m;
        m.x = xs.x + xr4.x; m.x = (m.x >= 0.f) ? m.x : 0.2f * m.x;
        m.y = xs.y + xr4.y; m.y = (m.y >= 0.f) ? m.y : 0.2f * m.y;
        m.z = xs.z + xr4.z; m.z = (m.z >= 0.f) ? m.z : 0.2f * m.z;
        m.w = xs.w + xr4.w; m.w = (m.w >= 0.f) ? m.w : 0.2f * m.w;
        float p = m.x*av.x + m.y*av.y + m.z*av.z + m.w*av.w;
        p += __shfl_xor_sync(0xffffffffu, p, 1);
        p += __shfl_xor_sync(0xffffffffu, p, 2);
        p += __shfl_xor_sync(0xffffffffu, p, 4);
        float wgt = __expf(p);
        den += wgt;
        acc.x += wgt * xs.x;
        acc.y += wgt * xs.y;
        acc.z += wgt * xs.z;
        acc.w += wgt * xs.w;
    }

    const float4 gb = *reinterpret_cast<const float4*>(&gbias[lane*4]);
    const float invd = 1.f / den;
    float4 h2;
    h2.x = acc.x * invd + gb.x;
    h2.y = acc.y * invd + gb.y;
    h2.z = acc.z * invd + gb.z;
    h2.w = acc.w * invd + gb.w;

    float my = 0.f;
    #pragma unroll
    for (int j = 0; j < 8; j++) {
        const float4 wq = *reinterpret_cast<const float4*>(&Wq[j*HIDD + lane*4]);
        float p = wq.x*h2.x + wq.y*h2.y + wq.z*h2.z + wq.w*h2.w;
        p += __shfl_xor_sync(0xffffffffu, p, 16);
        p += __shfl_xor_sync(0xffffffffu, p, 8);
        p += __shfl_xor_sync(0xffffffffu, p, 4);
        p += __shfl_xor_sync(0xffffffffu, p, 2);
        p += __shfl_xor_sync(0xffffffffu, p, 1);
        if (lane == j) my = p + bq[j];
    }
    if (lane < 8) out[(size_t)r * 8 + lane] = my;
}

// ---------------- launch ----------------
extern "C" void kernel_launch(void* const* d_in, const int* in_sizes, int n_in,
                              void* d_out, int out_size)
{
    const float* obs      = (const float*)d_in[0];
    const int*   ei       = (const int*)  d_in[1];
    const float* W_emb1   = (const float*)d_in[2];
    const float* b_emb1   = (const float*)d_in[3];
    const float* W_emb2   = (const float*)d_in[4];
    const float* b_emb2   = (const float*)d_in[5];
    const float* tf_wqkv  = (const float*)d_in[6];
    const float* tf_bqkv  = (const float*)d_in[7];
    const float* tf_wo    = (const float*)d_in[8];
    const float* tf_bo    = (const float*)d_in[9];
    const float* ffn_w1   = (const float*)d_in[10];
    const float* ffn_b1   = (const float*)d_in[11];
    const float* ffn_w2   = (const float*)d_in[12];
    const float* ffn_b2   = (const float*)d_in[13];
    const float* ln1_g    = (const float*)d_in[14];
    const float* ln1_b    = (const float*)d_in[15];
    const float* ln2_g    = (const float*)d_in[16];
    const float* ln2_b    = (const float*)d_in[17];
    const float* gat_wl   = (const float*)d_in[18];
    const float* gat_bl   = (const float*)d_in[19];
    const float* gat_wr   = (const float*)d_in[20];
    const float* gat_br   = (const float*)d_in[21];
    const float* gat_att  = (const float*)d_in[22];
    const float* gat_bias = (const float*)d_in[23];
    const float* W_q      = (const float*)d_in[24];
    const float* b_q      = (const float*)d_in[25];
    const float* pe       = (const float*)d_in[26];

    cudaFuncSetAttribute(kt_kernel, cudaFuncAttributeMaxDynamicSharedMemorySize, SM_KT * 4);
    cudaFuncSetAttribute(kdense,    cudaFuncAttributeMaxDynamicSharedMemorySize, SM_D * 4);

    kcsr<<<1, 256>>>(ei);
    kt_kernel<<<RTOT / 64, 256, SM_KT * 4>>>(obs,
        tf_wqkv, tf_bqkv, tf_wo, tf_bo,
        ffn_w1, ffn_b1, ffn_w2, ffn_b2,
        ln1_g, ln1_b, ln2_g, ln2_b, pe);
    kdense<<<RTOT / 128, 256, SM_D * 4>>>(W_emb1, b_emb1, W_emb2, b_emb2,
                                          gat_wl, gat_bl, gat_wr, gat_br);
    kgat<<<(RTOT * 32) / 256, 256>>>(gat_att, gat_bias, W_q, b_q, (float*)d_out);
}